// round 1
// baseline (speedup 1.0000x reference)
#include <cuda_runtime.h>
#include <math.h>

#define NB 8
#define NL 1024
#define NC 256
#define NH 8
#define HD 32
#define NT (NB*NL)   /* 8192 tokens */

static __device__ float g_qc[NT*NC];
static __device__ float g_kc[NT*NC];
static __device__ float g_vc[NT*NC];
static __device__ float g_qp[NT*NC];
static __device__ float g_kp[NT*NC];
static __device__ float g_vp[NT*NC];
static __device__ float g_ao[NT*NC];
static __device__ float g_part[3*64*2*NC];
static __device__ float g_ab[3*2*NC];
static __device__ float g_wf[3*NC*NC];
static __device__ float g_bf[3*NC];

// ---------------------------------------------------------------------------
// 3x3 conv, stride 1, pad 1, no bias.
// in : [B, L, C]  (token-major, channel contiguous; img[b,c,i,j] = in[b, i*32+j, c])
// w  : [Cout, Cin, 3, 3]
// out: [B*L, Cout]
// Block: 256 threads; tile = 4 output rows x 32 cols x 64 co.
// grid.x = B*8 (row groups of 4), grid.y = C/64.
// ---------------------------------------------------------------------------
__global__ __launch_bounds__(256) void conv3x3_kernel(
    const float* __restrict__ in, const float* __restrict__ w,
    float* __restrict__ out)
{
    const int j  = threadIdx.x & 31;   // spatial column
    const int g  = threadIdx.x >> 5;   // co group (8 co each)
    const int rg = blockIdx.x & 7;     // row group within batch
    const int b  = blockIdx.x >> 3;
    const int co0 = blockIdx.y * 64;
    const int r0 = rg * 4;

    __shared__ float s_in[6][8][34];   // rows r0-1..r0+4, 8 ci, cols -1..32
    __shared__ float s_w[64][8][9];

    float acc[4][8];
    #pragma unroll
    for (int ri = 0; ri < 4; ri++)
        #pragma unroll
        for (int k = 0; k < 8; k++) acc[ri][k] = 0.f;

    for (int ci0 = 0; ci0 < NC; ci0 += 8) {
        __syncthreads();
        // input slab: 6 rows x 34 cols x 8 ci (zero-padded borders)
        for (int idx = threadIdx.x; idx < 6*34*8; idx += 256) {
            int ciS = idx & 7;
            int p   = idx >> 3;
            int dr  = p / 34;
            int jj  = p - dr*34;
            int r   = r0 + dr - 1;
            int col = jj - 1;
            float v = 0.f;
            if ((unsigned)r < 32u && (unsigned)col < 32u)
                v = in[((b*NL) + r*32 + col)*NC + ci0 + ciS];
            s_in[dr][ciS][jj] = v;
        }
        // weights: 64 co x 8 ci x 9 taps
        for (int idx = threadIdx.x; idx < 64*8*9; idx += 256) {
            int tap = idx % 9;
            int rem = idx / 9;
            int ci  = rem & 7;
            int co  = rem >> 3;
            s_w[co][ci][tap] = w[((co0+co)*NC + ci0+ci)*9 + tap];
        }
        __syncthreads();

        #pragma unroll
        for (int ci = 0; ci < 8; ci++) {
            float iv[6][3];
            #pragma unroll
            for (int sr = 0; sr < 6; sr++) {
                iv[sr][0] = s_in[sr][ci][j];
                iv[sr][1] = s_in[sr][ci][j+1];
                iv[sr][2] = s_in[sr][ci][j+2];
            }
            #pragma unroll
            for (int k = 0; k < 8; k++) {
                const int co = g*8 + k;
                #pragma unroll
                for (int dr = 0; dr < 3; dr++) {
                    float w0 = s_w[co][ci][dr*3+0];
                    float w1 = s_w[co][ci][dr*3+1];
                    float w2 = s_w[co][ci][dr*3+2];
                    #pragma unroll
                    for (int ri = 0; ri < 4; ri++) {
                        acc[ri][k] += iv[ri+dr][0]*w0
                                    + iv[ri+dr][1]*w1
                                    + iv[ri+dr][2]*w2;
                    }
                }
            }
        }
    }

    #pragma unroll
    for (int ri = 0; ri < 4; ri++) {
        int t = b*NL + (r0+ri)*32 + j;
        #pragma unroll
        for (int k = 0; k < 8; k++)
            out[t*NC + co0 + g*8 + k] = acc[ri][k];
    }
}

// ---------------------------------------------------------------------------
// BN stats, stage 1: deterministic partial sums (no atomics).
// grid (64, 3), block 256. Thread = channel; block covers 128 tokens.
// ---------------------------------------------------------------------------
__global__ __launch_bounds__(256) void stats_partial_kernel(
    const float* __restrict__ q, const float* __restrict__ k,
    const float* __restrict__ v)
{
    const float* src = (blockIdx.y == 0) ? q : (blockIdx.y == 1) ? k : v;
    const int c = threadIdx.x;
    float s = 0.f, s2 = 0.f;
    const int t0 = blockIdx.x * (NT/64);
    for (int t = t0; t < t0 + NT/64; t++) {
        float val = src[t*NC + c];
        s  += val;
        s2 += val*val;
    }
    g_part[((blockIdx.y*64 + blockIdx.x)*2 + 0)*NC + c] = s;
    g_part[((blockIdx.y*64 + blockIdx.x)*2 + 1)*NC + c] = s2;
}

// BN stats, stage 2: mu/var -> per-channel affine (a, b):  x_norm = a*x + b
__global__ __launch_bounds__(256) void stats_final_kernel(
    const float* __restrict__ gq, const float* __restrict__ bq,
    const float* __restrict__ gk, const float* __restrict__ bk,
    const float* __restrict__ gv, const float* __restrict__ bv)
{
    const int s = blockIdx.x;
    const int c = threadIdx.x;
    float sum = 0.f, sum2 = 0.f;
    for (int i = 0; i < 64; i++) {
        sum  += g_part[((s*64+i)*2 + 0)*NC + c];
        sum2 += g_part[((s*64+i)*2 + 1)*NC + c];
    }
    float mu  = sum  * (1.f/NT);
    float var = sum2 * (1.f/NT) - mu*mu;
    const float* gam = (s == 0) ? gq : (s == 1) ? gk : gv;
    const float* bet = (s == 0) ? bq : (s == 1) ? bk : bv;
    float a  = gam[c] * rsqrtf(var + 1e-5f);
    float bb = bet[c] - mu*a;
    g_ab[(s*2+0)*NC + c] = a;
    g_ab[(s*2+1)*NC + c] = bb;
}

// Fold BN affine into projection weights: W'[co,c] = W[co,c]*a_c,
// bias[co] = sum_c W[co,c]*b_c.  grid (256, 3), block 256.
__global__ __launch_bounds__(256) void fold_kernel(
    const float* __restrict__ Wq, const float* __restrict__ Wk,
    const float* __restrict__ Wv)
{
    const int s  = blockIdx.y;
    const int co = blockIdx.x;
    const int c  = threadIdx.x;
    const float* W = (s == 0) ? Wq : (s == 1) ? Wk : Wv;
    float a  = g_ab[(s*2+0)*NC + c];
    float bb = g_ab[(s*2+1)*NC + c];
    float wv = W[co*NC + c];
    g_wf[s*NC*NC + co*NC + c] = wv * a;

    __shared__ float red[256];
    red[c] = wv * bb;
    __syncthreads();
    for (int o = 128; o > 0; o >>= 1) {
        if (c < o) red[c] += red[c + o];
        __syncthreads();
    }
    if (c == 0) g_bf[s*NC + co] = red[0];
}

// ---------------------------------------------------------------------------
// Tiled fp32 GEMM: out[t,n] = sum_k A[t,k]*W[n,k] + bias[n]
// A: [M, 256] row-major; W: [256, 256] row-major.
// split_heads=1 -> out laid out [B, H, L, d]; else [M, 256].
// Block 256 threads, tile 64x64, BK=16; grid (M/64, 4).
// ---------------------------------------------------------------------------
__global__ __launch_bounds__(256) void gemm_kernel(
    const float* __restrict__ A, const float* __restrict__ W,
    const float* __restrict__ bias, float* __restrict__ out,
    int split_heads)
{
    __shared__ float sA[16][64];
    __shared__ float sB[16][64];
    const int tx = threadIdx.x;
    const int m0 = blockIdx.x * 64;
    const int n0 = blockIdx.y * 64;
    const int tm = (tx >> 4) * 4;
    const int tn = (tx & 15) * 4;
    const int lrow = tx >> 2;        // 0..63
    const int lk   = (tx & 3) * 4;   // 0,4,8,12

    float acc[4][4] = {};

    for (int k0 = 0; k0 < NC; k0 += 16) {
        float4 av = *(const float4*)&A[(m0+lrow)*NC + k0 + lk];
        float4 wv = *(const float4*)&W[(n0+lrow)*NC + k0 + lk];
        sA[lk+0][lrow] = av.x; sA[lk+1][lrow] = av.y;
        sA[lk+2][lrow] = av.z; sA[lk+3][lrow] = av.w;
        sB[lk+0][lrow] = wv.x; sB[lk+1][lrow] = wv.y;
        sB[lk+2][lrow] = wv.z; sB[lk+3][lrow] = wv.w;
        __syncthreads();
        #pragma unroll
        for (int kk = 0; kk < 16; kk++) {
            float4 a4 = *(const float4*)&sA[kk][tm];
            float4 b4 = *(const float4*)&sB[kk][tn];
            float a[4] = {a4.x, a4.y, a4.z, a4.w};
            float bb[4] = {b4.x, b4.y, b4.z, b4.w};
            #pragma unroll
            for (int i = 0; i < 4; i++)
                #pragma unroll
                for (int jq = 0; jq < 4; jq++)
                    acc[i][jq] += a[i]*bb[jq];
        }
        __syncthreads();
    }

    #pragma unroll
    for (int i = 0; i < 4; i++) {
        const int t = m0 + tm + i;
        #pragma unroll
        for (int jq = 0; jq < 4; jq++) {
            const int n = n0 + tn + jq;
            float v = acc[i][jq] + bias[n];
            if (split_heads) {
                int bb = t >> 10, tb = t & 1023;
                int h = n >> 5,  d = n & 31;
                out[((bb*NH + h)*NL + tb)*HD + d] = v;
            } else {
                out[t*NC + n] = v;
            }
        }
    }
}

// ---------------------------------------------------------------------------
// Flash attention, fp32, scale = C^-0.5 = 1/16.
// Q,K,V: [B*H][L][32]; out written as [B, L, C] (b t (h d)).
// Block: 128 threads, 1 query row each; grid (64, 8).
// ---------------------------------------------------------------------------
__global__ __launch_bounds__(128) void attn_kernel(
    const float* __restrict__ Q, const float* __restrict__ K,
    const float* __restrict__ V, float* __restrict__ out)
{
    const int bh  = blockIdx.x;
    const int row = blockIdx.y * 128 + threadIdx.x;
    const float* Qb = Q + bh*NL*HD;
    const float* Kb = K + bh*NL*HD;
    const float* Vb = V + bh*NL*HD;

    const float scale = 0.0625f;
    float q[HD];
    #pragma unroll
    for (int i = 0; i < HD; i += 4) {
        float4 t4 = *(const float4*)&Qb[row*HD + i];
        q[i]   = t4.x*scale; q[i+1] = t4.y*scale;
        q[i+2] = t4.z*scale; q[i+3] = t4.w*scale;
    }

    float m = -1e30f, l = 0.f;
    float o[HD];
    #pragma unroll
    for (int i = 0; i < HD; i++) o[i] = 0.f;

    __shared__ float4 sk[64][8];
    __shared__ float4 sv[64][8];

    for (int k0 = 0; k0 < NL; k0 += 64) {
        __syncthreads();
        const float4* kg = (const float4*)(Kb + k0*HD);
        const float4* vg = (const float4*)(Vb + k0*HD);
        for (int i = threadIdx.x; i < 512; i += 128) {
            ((float4*)sk)[i] = kg[i];
            ((float4*)sv)[i] = vg[i];
        }
        __syncthreads();

        #pragma unroll 2
        for (int jj = 0; jj < 64; jj++) {
            float s = 0.f;
            #pragma unroll
            for (int u = 0; u < 8; u++) {
                float4 kv = sk[jj][u];
                s += q[4*u]*kv.x + q[4*u+1]*kv.y + q[4*u+2]*kv.z + q[4*u+3]*kv.w;
            }
            if (s > m) {
                float corr = __expf(m - s);
                l *= corr;
                #pragma unroll
                for (int i = 0; i < HD; i++) o[i] *= corr;
                m = s;
            }
            float p = __expf(s - m);
            l += p;
            #pragma unroll
            for (int u = 0; u < 8; u++) {
                float4 vv = sv[jj][u];
                o[4*u]   += p*vv.x; o[4*u+1] += p*vv.y;
                o[4*u+2] += p*vv.z; o[4*u+3] += p*vv.w;
            }
        }
    }

    const float inv = 1.f / l;
    const int b = bh >> 3, h = bh & 7;
    #pragma unroll
    for (int i = 0; i < HD; i++)
        out[(b*NL + row)*NC + h*HD + i] = o[i]*inv;
}

// ---------------------------------------------------------------------------

extern "C" void kernel_launch(void* const* d_in, const int* in_sizes, int n_in,
                              void* d_out, int out_size)
{
    const float* x        = (const float*)d_in[0];
    const float* y        = (const float*)d_in[1];
    // d_in[2], d_in[3]: h, w (fixed 32x32)
    const float* conv_q_w = (const float*)d_in[4];
    const float* bn_q_g   = (const float*)d_in[5];
    const float* bn_q_b   = (const float*)d_in[6];
    const float* conv_k_w = (const float*)d_in[7];
    const float* bn_k_g   = (const float*)d_in[8];
    const float* bn_k_b   = (const float*)d_in[9];
    const float* conv_v_w = (const float*)d_in[10];
    const float* bn_v_g   = (const float*)d_in[11];
    const float* bn_v_b   = (const float*)d_in[12];
    const float* Wq       = (const float*)d_in[13];
    const float* Wk       = (const float*)d_in[14];
    const float* Wv       = (const float*)d_in[15];
    const float* Wo       = (const float*)d_in[16];
    const float* bo       = (const float*)d_in[17];
    float* out = (float*)d_out;

    float *qc, *kc, *vc, *qp, *kp, *vp, *ao, *wf, *bf;
    cudaGetSymbolAddress((void**)&qc, g_qc);
    cudaGetSymbolAddress((void**)&kc, g_kc);
    cudaGetSymbolAddress((void**)&vc, g_vc);
    cudaGetSymbolAddress((void**)&qp, g_qp);
    cudaGetSymbolAddress((void**)&kp, g_kp);
    cudaGetSymbolAddress((void**)&vp, g_vp);
    cudaGetSymbolAddress((void**)&ao, g_ao);
    cudaGetSymbolAddress((void**)&wf, g_wf);
    cudaGetSymbolAddress((void**)&bf, g_bf);

    dim3 cg(NB*8, NC/64);
    conv3x3_kernel<<<cg, 256>>>(x, conv_q_w, qc);
    conv3x3_kernel<<<cg, 256>>>(y, conv_k_w, kc);
    conv3x3_kernel<<<cg, 256>>>(y, conv_v_w, vc);

    stats_partial_kernel<<<dim3(64,3), 256>>>(qc, kc, vc);
    stats_final_kernel<<<3, 256>>>(bn_q_g, bn_q_b, bn_k_g, bn_k_b, bn_v_g, bn_v_b);
    fold_kernel<<<dim3(NC,3), 256>>>(Wq, Wk, Wv);

    gemm_kernel<<<dim3(NT/64, NC/64), 256>>>(qc, wf,            bf,        qp, 1);
    gemm_kernel<<<dim3(NT/64, NC/64), 256>>>(kc, wf + NC*NC,    bf + NC,   kp, 1);
    gemm_kernel<<<dim3(NT/64, NC/64), 256>>>(vc, wf + 2*NC*NC,  bf + 2*NC, vp, 1);

    attn_kernel<<<dim3(NB*NH, NL/128), 128>>>(qp, kp, vp, ao);

    gemm_kernel<<<dim3(NT/64, NC/64), 256>>>(ao, Wo, bo, out, 0);
}

// round 3
// speedup vs baseline: 2.0835x; 2.0835x over previous
#include <cuda_runtime.h>
#include <math.h>
#include <cstdint>

#define NB 8
#define NL 1024
#define NC 256
#define NH 8
#define HD 32
#define NT (NB*NL)   /* 8192 tokens */

// ------------------------- scratch (device globals) -------------------------
static __device__ float g_qc[NT*NC];
static __device__ float g_kc[NT*NC];
static __device__ float g_vc[NT*NC];
static __device__ float g_qp[NT*NC];
static __device__ float g_kp[NT*NC];
static __device__ float g_vp[NT*NC];
static __device__ float g_ao[NT*NC];
static __device__ float g_part[3*64*2*NC];
static __device__ float g_ab[3*2*NC];
static __device__ float g_wf[3*NC*NC];
static __device__ float g_bf[3*NC];
static __device__ float g_wt[3*9*NC*NC];   // conv weights as [conv][tap][co][ci]

__device__ __forceinline__ uint32_t to_tf32(float f) {
    uint32_t r;
    asm("cvt.rna.tf32.f32 %0, %1;" : "=r"(r) : "f"(f));
    return r;
}

// ---------------------------------------------------------------------------
// Tensor-core GEMM via mma.sync m16n8k8 tf32 (classic HMMA path, sm_103 base).
//   plain GEMM : out[t,n] = sum_k A[t,k]*Bw[n,k]            (conv=0, K=256)
//   implicit conv: K = 9 taps x 256 ci, A gathered w/ spatial shift (conv=1)
// Block 256 threads (8 warps, 2x4), tile M=128 x N=128, K-chunk 32.
// smem tiles padded to stride 36 floats -> conflict-free fragment LDS.
// split=1 writes [B,H,L,d]; bias optional.
// ---------------------------------------------------------------------------
#define KS 36   /* smem row stride in floats */

__global__ __launch_bounds__(256) void mma_gemm_kernel(
    const float* __restrict__ A, const float* __restrict__ Bw,
    const float* __restrict__ bias, float* __restrict__ out,
    int conv, int split)
{
    __shared__ uint32_t sA[128*KS];
    __shared__ uint32_t sB[128*KS];

    const int tid = threadIdx.x;
    const int wid = tid >> 5;
    const int lane = tid & 31;
    const int gID = lane >> 2;    // 0..7
    const int tq  = lane & 3;     // 0..3
    const int wm = (wid >> 2) * 64;   // warp m offset (0/64)
    const int wn = (wid & 3) * 32;    // warp n offset (0/32/64/96)

    const int m0 = blockIdx.x * 128;
    const int n0 = blockIdx.y * 128;
    const int bImg = m0 >> 10;
    const int r0   = (m0 >> 5) & 31;
    const int nch  = conv ? 72 : 8;

    float acc[4][4][4];
    #pragma unroll
    for (int i = 0; i < 4; i++)
        #pragma unroll
        for (int j = 0; j < 4; j++)
            #pragma unroll
            for (int c = 0; c < 4; c++) acc[i][j][c] = 0.f;

    for (int ch = 0; ch < nch; ch++) {
        const int tap = conv ? (ch >> 3) : 0;
        const int k0  = (conv ? (ch & 7) : ch) * 32;
        const int dr  = tap / 3 - 1, dc = tap % 3 - 1;

        __syncthreads();
        // A tile: 128 rows x 32 floats (1024 float4, 4 per thread)
        #pragma unroll
        for (int u = 0; u < 4; u++) {
            const int f4  = u * 256 + tid;
            const int row = f4 >> 3, c4 = f4 & 7;
            float4 v = make_float4(0.f, 0.f, 0.f, 0.f);
            if (conv) {
                const int lr = row >> 5, col = row & 31;
                const int gr = r0 + lr + dr, gc = col + dc;
                if ((unsigned)gr < 32u && (unsigned)gc < 32u)
                    v = *(const float4*)&A[(((bImg << 10) + gr*32 + gc) << 8) + k0 + c4*4];
            } else {
                v = *(const float4*)&A[((m0 + row) << 8) + k0 + c4*4];
            }
            uint32_t* d = &sA[row*KS + c4*4];
            d[0] = to_tf32(v.x); d[1] = to_tf32(v.y);
            d[2] = to_tf32(v.z); d[3] = to_tf32(v.w);
        }
        // B tile: 128 rows (n) x 32 floats
        #pragma unroll
        for (int u = 0; u < 4; u++) {
            const int f4  = u * 256 + tid;
            const int row = f4 >> 3, c4 = f4 & 7;
            float4 v;
            if (conv) v = *(const float4*)&Bw[((tap*256 + n0 + row) << 8) + k0 + c4*4];
            else      v = *(const float4*)&Bw[((n0 + row) << 8) + k0 + c4*4];
            uint32_t* d = &sB[row*KS + c4*4];
            d[0] = to_tf32(v.x); d[1] = to_tf32(v.y);
            d[2] = to_tf32(v.z); d[3] = to_tf32(v.w);
        }
        __syncthreads();

        #pragma unroll
        for (int kk = 0; kk < 32; kk += 8) {
            uint32_t af[4][4];
            #pragma unroll
            for (int mt = 0; mt < 4; mt++) {
                const uint32_t* base = &sA[(wm + mt*16 + gID)*KS + kk + tq];
                af[mt][0] = base[0];
                af[mt][1] = base[8*KS];
                af[mt][2] = base[4];
                af[mt][3] = base[8*KS + 4];
            }
            uint32_t bf2[4][2];
            #pragma unroll
            for (int nt = 0; nt < 4; nt++) {
                const uint32_t* base = &sB[(wn + nt*8 + gID)*KS + kk + tq];
                bf2[nt][0] = base[0];
                bf2[nt][1] = base[4];
            }
            #pragma unroll
            for (int mt = 0; mt < 4; mt++)
                #pragma unroll
                for (int nt = 0; nt < 4; nt++) {
                    asm volatile(
                        "mma.sync.aligned.m16n8k8.row.col.f32.tf32.tf32.f32 "
                        "{%0,%1,%2,%3}, {%4,%5,%6,%7}, {%8,%9}, {%0,%1,%2,%3};"
                        : "+f"(acc[mt][nt][0]), "+f"(acc[mt][nt][1]),
                          "+f"(acc[mt][nt][2]), "+f"(acc[mt][nt][3])
                        : "r"(af[mt][0]), "r"(af[mt][1]), "r"(af[mt][2]), "r"(af[mt][3]),
                          "r"(bf2[nt][0]), "r"(bf2[nt][1]));
                }
        }
    }

    // epilogue
    #pragma unroll
    for (int mt = 0; mt < 4; mt++) {
        #pragma unroll
        for (int half = 0; half < 2; half++) {
            const int t = m0 + wm + mt*16 + gID + half*8;
            #pragma unroll
            for (int nt = 0; nt < 4; nt++) {
                const int n = n0 + wn + nt*8 + tq*2;
                float v0 = acc[mt][nt][half*2 + 0];
                float v1 = acc[mt][nt][half*2 + 1];
                if (bias) { v0 += bias[n]; v1 += bias[n+1]; }
                if (split) {
                    const int bb = t >> 10, tt = t & 1023;
                    const int h = n >> 5,  d = n & 31;
                    float* p = &out[((bb*NH + h)*NL + tt)*HD + d];
                    p[0] = v0; p[1] = v1;
                } else {
                    out[t*NC + n]     = v0;
                    out[t*NC + n + 1] = v1;
                }
            }
        }
    }
}

// ----------------- conv weight transform: w[co][ci][tap] -> wt[tap][co][ci] -
__global__ __launch_bounds__(256) void wtrans_kernel(
    const float* __restrict__ wq, const float* __restrict__ wk,
    const float* __restrict__ wv)
{
    const float* W = (blockIdx.y == 0) ? wq : (blockIdx.y == 1) ? wk : wv;
    float* dst = g_wt + blockIdx.y * 9*NC*NC;
    const int idx = blockIdx.x * 256 + threadIdx.x;   // (tap*256+co)*256+ci
    const int ci  = idx & 255;
    const int rem = idx >> 8;
    const int co  = rem & 255;
    const int tap = rem >> 8;
    dst[idx] = W[(co*NC + ci)*9 + tap];
}

// --------------------------- BN stats + fold --------------------------------
__global__ __launch_bounds__(256) void stats_partial_kernel(
    const float* __restrict__ q, const float* __restrict__ k,
    const float* __restrict__ v)
{
    const float* src = (blockIdx.y == 0) ? q : (blockIdx.y == 1) ? k : v;
    const int c = threadIdx.x;
    float s = 0.f, s2 = 0.f;
    const int t0 = blockIdx.x * (NT/64);
    for (int t = t0; t < t0 + NT/64; t++) {
        float val = src[t*NC + c];
        s += val; s2 += val*val;
    }
    g_part[((blockIdx.y*64 + blockIdx.x)*2 + 0)*NC + c] = s;
    g_part[((blockIdx.y*64 + blockIdx.x)*2 + 1)*NC + c] = s2;
}

__global__ __launch_bounds__(256) void stats_final_kernel(
    const float* __restrict__ gq, const float* __restrict__ bq,
    const float* __restrict__ gk, const float* __restrict__ bk,
    const float* __restrict__ gv, const float* __restrict__ bv)
{
    const int s = blockIdx.x;
    const int c = threadIdx.x;
    float sum = 0.f, sum2 = 0.f;
    for (int i = 0; i < 64; i++) {
        sum  += g_part[((s*64+i)*2 + 0)*NC + c];
        sum2 += g_part[((s*64+i)*2 + 1)*NC + c];
    }
    float mu  = sum  * (1.f/NT);
    float var = sum2 * (1.f/NT) - mu*mu;
    const float* gam = (s == 0) ? gq : (s == 1) ? gk : gv;
    const float* bet = (s == 0) ? bq : (s == 1) ? bk : bv;
    float a  = gam[c] * rsqrtf(var + 1e-5f);
    float bb = bet[c] - mu*a;
    g_ab[(s*2+0)*NC + c] = a;
    g_ab[(s*2+1)*NC + c] = bb;
}

__global__ __launch_bounds__(256) void fold_kernel(
    const float* __restrict__ Wq, const float* __restrict__ Wk,
    const float* __restrict__ Wv)
{
    const int s  = blockIdx.y;
    const int co = blockIdx.x;
    const int c  = threadIdx.x;
    const float* W = (s == 0) ? Wq : (s == 1) ? Wk : Wv;
    float a  = g_ab[(s*2+0)*NC + c];
    float bb = g_ab[(s*2+1)*NC + c];
    float wv = W[co*NC + c];
    g_wf[s*NC*NC + co*NC + c] = wv * a;

    __shared__ float red[256];
    red[c] = wv * bb;
    __syncthreads();
    for (int o = 128; o > 0; o >>= 1) {
        if (c < o) red[c] += red[c + o];
        __syncthreads();
    }
    if (c == 0) g_bf[s*NC + co] = red[0];
}

// ------------------------- flash attention (scalar fp32) --------------------
__global__ __launch_bounds__(128) void attn_kernel(
    const float* __restrict__ Q, const float* __restrict__ K,
    const float* __restrict__ V, float* __restrict__ out)
{
    const int bh  = blockIdx.x;
    const int row = blockIdx.y * 128 + threadIdx.x;
    const float* Qb = Q + bh*NL*HD;
    const float* Kb = K + bh*NL*HD;
    const float* Vb = V + bh*NL*HD;

    const float scale = 0.0625f;
    float q[HD];
    #pragma unroll
    for (int i = 0; i < HD; i += 4) {
        float4 t4 = *(const float4*)&Qb[row*HD + i];
        q[i] = t4.x*scale; q[i+1] = t4.y*scale;
        q[i+2] = t4.z*scale; q[i+3] = t4.w*scale;
    }

    float m = -1e30f, l = 0.f;
    float o[HD];
    #pragma unroll
    for (int i = 0; i < HD; i++) o[i] = 0.f;

    __shared__ float4 sk[64][8];
    __shared__ float4 sv[64][8];

    for (int k0 = 0; k0 < NL; k0 += 64) {
        __syncthreads();
        const float4* kg = (const float4*)(Kb + k0*HD);
        const float4* vg = (const float4*)(Vb + k0*HD);
        for (int i = threadIdx.x; i < 512; i += 128) {
            ((float4*)sk)[i] = kg[i];
            ((float4*)sv)[i] = vg[i];
        }
        __syncthreads();

        #pragma unroll 2
        for (int jj = 0; jj < 64; jj++) {
            float s = 0.f;
            #pragma unroll
            for (int u = 0; u < 8; u++) {
                float4 kv = sk[jj][u];
                s += q[4*u]*kv.x + q[4*u+1]*kv.y + q[4*u+2]*kv.z + q[4*u+3]*kv.w;
            }
            if (s > m) {
                float corr = __expf(m - s);
                l *= corr;
                #pragma unroll
                for (int i = 0; i < HD; i++) o[i] *= corr;
                m = s;
            }
            float p = __expf(s - m);
            l += p;
            #pragma unroll
            for (int u = 0; u < 8; u++) {
                float4 vv = sv[jj][u];
                o[4*u]   += p*vv.x; o[4*u+1] += p*vv.y;
                o[4*u+2] += p*vv.z; o[4*u+3] += p*vv.w;
            }
        }
    }

    const float inv = 1.f / l;
    const int b = bh >> 3, h = bh & 7;
    #pragma unroll
    for (int i = 0; i < HD; i++)
        out[(b*NL + row)*NC + h*HD + i] = o[i]*inv;
}

// ---------------------------------------------------------------------------

extern "C" void kernel_launch(void* const* d_in, const int* in_sizes, int n_in,
                              void* d_out, int out_size)
{
    const float* x        = (const float*)d_in[0];
    const float* y        = (const float*)d_in[1];
    const float* conv_q_w = (const float*)d_in[4];
    const float* bn_q_g   = (const float*)d_in[5];
    const float* bn_q_b   = (const float*)d_in[6];
    const float* conv_k_w = (const float*)d_in[7];
    const float* bn_k_g   = (const float*)d_in[8];
    const float* bn_k_b   = (const float*)d_in[9];
    const float* conv_v_w = (const float*)d_in[10];
    const float* bn_v_g   = (const float*)d_in[11];
    const float* bn_v_b   = (const float*)d_in[12];
    const float* Wq       = (const float*)d_in[13];
    const float* Wk       = (const float*)d_in[14];
    const float* Wv       = (const float*)d_in[15];
    const float* Wo       = (const float*)d_in[16];
    const float* bo       = (const float*)d_in[17];
    float* out = (float*)d_out;

    float *qc, *kc, *vc, *qp, *kp, *vp, *ao, *wf, *bf, *wt;
    cudaGetSymbolAddress((void**)&qc, g_qc);
    cudaGetSymbolAddress((void**)&kc, g_kc);
    cudaGetSymbolAddress((void**)&vc, g_vc);
    cudaGetSymbolAddress((void**)&qp, g_qp);
    cudaGetSymbolAddress((void**)&kp, g_kp);
    cudaGetSymbolAddress((void**)&vp, g_vp);
    cudaGetSymbolAddress((void**)&ao, g_ao);
    cudaGetSymbolAddress((void**)&wf, g_wf);
    cudaGetSymbolAddress((void**)&bf, g_bf);
    cudaGetSymbolAddress((void**)&wt, g_wt);

    // conv weight layout transform
    wtrans_kernel<<<dim3(9*NC, 3), 256>>>(conv_q_w, conv_k_w, conv_v_w);

    // convs as implicit GEMM on tensor cores (HMMA)
    dim3 gg(NT/128, NC/128);
    mma_gemm_kernel<<<gg, 256>>>(x, wt,            nullptr, qc, 1, 0);
    mma_gemm_kernel<<<gg, 256>>>(y, wt + 9*NC*NC,  nullptr, kc, 1, 0);
    mma_gemm_kernel<<<gg, 256>>>(y, wt + 18*NC*NC, nullptr, vc, 1, 0);

    // BN stats -> fold into projection weights
    stats_partial_kernel<<<dim3(64,3), 256>>>(qc, kc, vc);
    stats_final_kernel<<<3, 256>>>(bn_q_g, bn_q_b, bn_k_g, bn_k_b, bn_v_g, bn_v_b);
    fold_kernel<<<dim3(NC,3), 256>>>(Wq, Wk, Wv);

    // projections (BN-folded) on tensor cores, split-head output
    mma_gemm_kernel<<<gg, 256>>>(qc, wf,           bf,        qp, 0, 1);
    mma_gemm_kernel<<<gg, 256>>>(kc, wf + NC*NC,   bf + NC,   kp, 0, 1);
    mma_gemm_kernel<<<gg, 256>>>(vc, wf + 2*NC*NC, bf + 2*NC, vp, 0, 1);

    attn_kernel<<<dim3(NB*NH, NL/128), 128>>>(qp, kp, vp, ao);

    // output projection
    mma_gemm_kernel<<<gg, 256>>>(ao, Wo, bo, out, 0, 0);
}

// round 4
// speedup vs baseline: 3.2881x; 1.5782x over previous
#include <cuda_runtime.h>
#include <math.h>
#include <cstdint>

#define NB 8
#define NL 1024
#define NC 256
#define NH 8
#define HD 32
#define NT (NB*NL)   /* 8192 tokens */

// ------------------------- scratch (device globals) -------------------------
static __device__ float g_cv[3*NT*NC];     // conv outputs q/k/v
static __device__ float g_pr[3*NT*NC];     // projected q/k/v [B,H,L,d]
static __device__ float g_ao[NT*NC];       // attention output [B,L,C]
static __device__ float g_part[3*64*2*NC];
static __device__ float g_ab[3*2*NC];
static __device__ float g_wf[3*NC*NC];
static __device__ float g_bf[3*NC];
static __device__ float g_wt[3*9*NC*NC];   // conv weights as [conv][tap][co][ci]

// ------------------------------ helpers -------------------------------------
__device__ __forceinline__ uint32_t to_tf32(float f) {
    uint32_t r;
    asm("cvt.rna.tf32.f32 %0, %1;" : "=r"(r) : "f"(f));
    return r;
}
__device__ __forceinline__ uint32_t cvta_s(const void* p) {
    return (uint32_t)__cvta_generic_to_shared(p);
}
__device__ __forceinline__ void cp16(uint32_t d, const void* s, uint32_t sz) {
    asm volatile("cp.async.cg.shared.global [%0], [%1], 16, %2;"
                 :: "r"(d), "l"(s), "r"(sz));
}
#define CP_COMMIT() asm volatile("cp.async.commit_group;")
#define CP_WAIT1()  asm volatile("cp.async.wait_group 1;")
#define CP_WAIT0()  asm volatile("cp.async.wait_group 0;")

__device__ __forceinline__ void mma_tf32(float* c, const uint32_t* a, const uint32_t* b) {
    asm volatile(
        "mma.sync.aligned.m16n8k8.row.col.f32.tf32.tf32.f32 "
        "{%0,%1,%2,%3}, {%4,%5,%6,%7}, {%8,%9}, {%0,%1,%2,%3};"
        : "+f"(c[0]), "+f"(c[1]), "+f"(c[2]), "+f"(c[3])
        : "r"(a[0]), "r"(a[1]), "r"(a[2]), "r"(a[3]), "r"(b[0]), "r"(b[1]));
}

// ---------------------------------------------------------------------------
// Pipelined tensor-core GEMM (m16n8k8 tf32), tile M=128 x N=128, K-chunk 32.
//   conv=1: implicit 3x3 conv, K = 9 taps x 256 ci
//   conv=0: plain GEMM K=256
// grid.z selects {input, weight slab, bias slab, output slab}.
// 2-stage cp.async double buffer, raw fp32 in smem, RNA->tf32 at fragment load.
// ---------------------------------------------------------------------------
#define KS 36   /* smem row stride (floats) */

__global__ __launch_bounds__(256, 2) void mma_gemm_kernel(
    const float* __restrict__ A0, const float* __restrict__ A1,
    const float* __restrict__ A2,
    const float* __restrict__ Bw0, long bStride,
    const float* __restrict__ bias0, float* __restrict__ out0, long oStride,
    int conv, int split)
{
    extern __shared__ float sm[];
    float* sA[2] = { sm,            sm + 128*KS };
    float* sB[2] = { sm + 2*128*KS, sm + 3*128*KS };

    const int z = blockIdx.z;
    const float* A    = (z == 0) ? A0 : ((z == 1) ? A1 : A2);
    const float* Bw   = Bw0 + (long)z * bStride;
    const float* bias = bias0 ? (bias0 + z*NC) : nullptr;
    float* out        = out0 + (long)z * oStride;

    const int tid = threadIdx.x;
    const int wid = tid >> 5, lane = tid & 31;
    const int gID = lane >> 2, tq = lane & 3;
    const int wm = (wid >> 2) * 64, wn = (wid & 3) * 32;
    const int m0 = blockIdx.x * 128, n0 = blockIdx.y * 128;
    const int bImg = m0 >> 10, r0 = (m0 >> 5) & 31;
    const int nch = conv ? 72 : 8;

    auto load_stage = [&](int ch, int st) {
        const int tap = conv ? (ch >> 3) : 0;
        const int k0  = (conv ? (ch & 7) : ch) * 32;
        const int dr = tap/3 - 1, dc = tap%3 - 1;
        #pragma unroll
        for (int u = 0; u < 4; u++) {
            const int f4 = u*256 + tid, row = f4 >> 3, c4 = f4 & 7;
            uint32_t dst = cvta_s(&sA[st][row*KS + c4*4]);
            const float* src; uint32_t sz = 16;
            if (conv) {
                const int lr = row >> 5, col = row & 31;
                const int gr = r0 + lr + dr, gc = col + dc;
                src = &A[(((bImg << 10) + gr*32 + gc) << 8) + k0 + c4*4];
                if (!((unsigned)gr < 32u && (unsigned)gc < 32u)) { sz = 0; src = A; }
            } else {
                src = &A[((m0 + row) << 8) + k0 + c4*4];
            }
            cp16(dst, src, sz);
        }
        #pragma unroll
        for (int u = 0; u < 4; u++) {
            const int f4 = u*256 + tid, row = f4 >> 3, c4 = f4 & 7;
            uint32_t dst = cvta_s(&sB[st][row*KS + c4*4]);
            const float* src = conv ? &Bw[((tap*256 + n0 + row) << 8) + k0 + c4*4]
                                    : &Bw[((n0 + row) << 8) + k0 + c4*4];
            cp16(dst, src, 16);
        }
    };

    float acc[4][4][4];
    #pragma unroll
    for (int i = 0; i < 4; i++)
        #pragma unroll
        for (int j = 0; j < 4; j++)
            #pragma unroll
            for (int c = 0; c < 4; c++) acc[i][j][c] = 0.f;

    load_stage(0, 0); CP_COMMIT();

    for (int ch = 0; ch < nch; ch++) {
        const int cur = ch & 1;
        if (ch + 1 < nch) { load_stage(ch + 1, cur ^ 1); CP_COMMIT(); CP_WAIT1(); }
        else              { CP_WAIT0(); }
        __syncthreads();

        #pragma unroll
        for (int kk = 0; kk < 32; kk += 8) {
            uint32_t af[4][4];
            #pragma unroll
            for (int mt = 0; mt < 4; mt++) {
                const float* base = &sA[cur][(wm + mt*16 + gID)*KS + kk + tq];
                af[mt][0] = to_tf32(base[0]);
                af[mt][1] = to_tf32(base[8*KS]);
                af[mt][2] = to_tf32(base[4]);
                af[mt][3] = to_tf32(base[8*KS + 4]);
            }
            uint32_t bf2[4][2];
            #pragma unroll
            for (int nt = 0; nt < 4; nt++) {
                const float* base = &sB[cur][(wn + nt*8 + gID)*KS + kk + tq];
                bf2[nt][0] = to_tf32(base[0]);
                bf2[nt][1] = to_tf32(base[4]);
            }
            #pragma unroll
            for (int mt = 0; mt < 4; mt++)
                #pragma unroll
                for (int nt = 0; nt < 4; nt++)
                    mma_tf32(acc[mt][nt], af[mt], bf2[nt]);
        }
        __syncthreads();
    }

    // epilogue
    #pragma unroll
    for (int mt = 0; mt < 4; mt++) {
        #pragma unroll
        for (int half = 0; half < 2; half++) {
            const int t = m0 + wm + mt*16 + gID + half*8;
            #pragma unroll
            for (int nt = 0; nt < 4; nt++) {
                const int n = n0 + wn + nt*8 + tq*2;
                float v0 = acc[mt][nt][half*2 + 0];
                float v1 = acc[mt][nt][half*2 + 1];
                if (bias) { v0 += bias[n]; v1 += bias[n+1]; }
                if (split) {
                    const int bb = t >> 10, tt = t & 1023;
                    const int h = n >> 5, d = n & 31;
                    float* p = &out[((bb*NH + h)*NL + tt)*HD + d];
                    p[0] = v0; p[1] = v1;
                } else {
                    out[t*NC + n]     = v0;
                    out[t*NC + n + 1] = v1;
                }
            }
        }
    }
}

// ---------------------------------------------------------------------------
// Tensor-core flash attention (tf32 mma, fp32 softmax).
// Block = 128 threads (4 warps); each warp owns 16 q rows; block = 64 q rows.
// grid (64 bh, 16 q-tiles). K/V double-buffered via cp.async.
// ---------------------------------------------------------------------------
#define VS 40   /* V smem stride */
#define PS 68   /* P smem stride */

__global__ __launch_bounds__(128) void attn_mma_kernel(
    const float* __restrict__ Q, const float* __restrict__ K,
    const float* __restrict__ V, float* __restrict__ out)
{
    extern __shared__ float sm[];
    float* sK[2] = { sm, sm + 64*KS };
    float* sV[2] = { sm + 2*64*KS, sm + 2*64*KS + 64*VS };
    float* sP    = sm + 2*64*KS + 2*64*VS;   // 64 x PS

    const int bh = blockIdx.x, qt = blockIdx.y;
    const int tid = threadIdx.x, w = tid >> 5, lane = tid & 31;
    const int gID = lane >> 2, tq = lane & 3;
    const int r0 = qt*64 + w*16;
    const float* Qb = Q + (long)bh*NL*HD;
    const float* Kb = K + (long)bh*NL*HD;
    const float* Vb = V + (long)bh*NL*HD;

    const float scale = 0.0625f;   // 1/sqrt(256)
    uint32_t qf[4][4];
    #pragma unroll
    for (int ks = 0; ks < 4; ks++) {
        qf[ks][0] = to_tf32(Qb[(r0+gID  )*HD + ks*8 + tq    ] * scale);
        qf[ks][1] = to_tf32(Qb[(r0+gID+8)*HD + ks*8 + tq    ] * scale);
        qf[ks][2] = to_tf32(Qb[(r0+gID  )*HD + ks*8 + tq + 4] * scale);
        qf[ks][3] = to_tf32(Qb[(r0+gID+8)*HD + ks*8 + tq + 4] * scale);
    }

    float m0 = -1e30f, m1 = -1e30f, l0 = 0.f, l1 = 0.f;
    float oacc[4][4];
    #pragma unroll
    for (int i = 0; i < 4; i++)
        #pragma unroll
        for (int j = 0; j < 4; j++) oacc[i][j] = 0.f;

    auto load_kv = [&](int kt, int st) {
        #pragma unroll
        for (int u = 0; u < 4; u++) {
            const int idx = u*128 + tid, row = idx >> 3, c4 = idx & 7;
            cp16(cvta_s(&sK[st][row*KS + c4*4]), &Kb[(kt*64 + row)*HD + c4*4], 16);
            cp16(cvta_s(&sV[st][row*VS + c4*4]), &Vb[(kt*64 + row)*HD + c4*4], 16);
        }
    };

    load_kv(0, 0); CP_COMMIT();

    for (int kt = 0; kt < 16; kt++) {
        const int cur = kt & 1;
        if (kt + 1 < 16) { load_kv(kt + 1, cur ^ 1); CP_COMMIT(); CP_WAIT1(); }
        else             { CP_WAIT0(); }
        __syncthreads();

        // S = Q K^T (16 x 64 per warp)
        float sacc[8][4];
        #pragma unroll
        for (int nt = 0; nt < 8; nt++)
            #pragma unroll
            for (int c = 0; c < 4; c++) sacc[nt][c] = 0.f;
        #pragma unroll
        for (int kk = 0; kk < 4; kk++) {
            #pragma unroll
            for (int nt = 0; nt < 8; nt++) {
                uint32_t b[2];
                const float* base = &sK[cur][(nt*8 + gID)*KS + kk*8 + tq];
                b[0] = to_tf32(base[0]);
                b[1] = to_tf32(base[4]);
                mma_tf32(sacc[nt], qf[kk], b);
            }
        }

        // online softmax (rows gID and gID+8 of this warp's 16)
        float mx0 = -1e30f, mx1 = -1e30f;
        #pragma unroll
        for (int nt = 0; nt < 8; nt++) {
            mx0 = fmaxf(mx0, fmaxf(sacc[nt][0], sacc[nt][1]));
            mx1 = fmaxf(mx1, fmaxf(sacc[nt][2], sacc[nt][3]));
        }
        mx0 = fmaxf(mx0, __shfl_xor_sync(~0u, mx0, 1));
        mx0 = fmaxf(mx0, __shfl_xor_sync(~0u, mx0, 2));
        mx1 = fmaxf(mx1, __shfl_xor_sync(~0u, mx1, 1));
        mx1 = fmaxf(mx1, __shfl_xor_sync(~0u, mx1, 2));
        const float mn0 = fmaxf(m0, mx0), mn1 = fmaxf(m1, mx1);
        const float c0 = __expf(m0 - mn0), c1 = __expf(m1 - mn1);

        float s0 = 0.f, s1 = 0.f;
        #pragma unroll
        for (int nt = 0; nt < 8; nt++) {
            float p0 = __expf(sacc[nt][0] - mn0);
            float p1 = __expf(sacc[nt][1] - mn0);
            float p2 = __expf(sacc[nt][2] - mn1);
            float p3 = __expf(sacc[nt][3] - mn1);
            s0 += p0 + p1; s1 += p2 + p3;
            float* pr  = &sP[(w*16 + gID    )*PS + nt*8 + tq*2];
            float* pr2 = &sP[(w*16 + gID + 8)*PS + nt*8 + tq*2];
            pr[0]  = __uint_as_float(to_tf32(p0));
            pr[1]  = __uint_as_float(to_tf32(p1));
            pr2[0] = __uint_as_float(to_tf32(p2));
            pr2[1] = __uint_as_float(to_tf32(p3));
        }
        s0 += __shfl_xor_sync(~0u, s0, 1); s0 += __shfl_xor_sync(~0u, s0, 2);
        s1 += __shfl_xor_sync(~0u, s1, 1); s1 += __shfl_xor_sync(~0u, s1, 2);
        l0 = l0*c0 + s0; l1 = l1*c1 + s1;
        #pragma unroll
        for (int nt = 0; nt < 4; nt++) {
            oacc[nt][0] *= c0; oacc[nt][1] *= c0;
            oacc[nt][2] *= c1; oacc[nt][3] *= c1;
        }
        m0 = mn0; m1 = mn1;
        __syncwarp();

        // O += P V  (16 x 32 per warp)
        #pragma unroll
        for (int kk = 0; kk < 8; kk++) {
            uint32_t pa[4];
            const float* pb = &sP[(w*16 + gID)*PS + kk*8 + tq];
            pa[0] = __float_as_uint(pb[0]);
            pa[1] = __float_as_uint(pb[8*PS]);
            pa[2] = __float_as_uint(pb[4]);
            pa[3] = __float_as_uint(pb[8*PS + 4]);
            #pragma unroll
            for (int nt = 0; nt < 4; nt++) {
                uint32_t vb[2];
                vb[0] = to_tf32(sV[cur][(kk*8 + tq    )*VS + nt*8 + gID]);
                vb[1] = to_tf32(sV[cur][(kk*8 + tq + 4)*VS + nt*8 + gID]);
                mma_tf32(oacc[nt], pa, vb);
            }
        }
        __syncthreads();
    }

    const float i0 = 1.f / l0, i1 = 1.f / l1;
    const int b = bh >> 3, h = bh & 7;
    #pragma unroll
    for (int nt = 0; nt < 4; nt++) {
        const int col = h*HD + nt*8 + tq*2;
        float2 v0 = { oacc[nt][0]*i0, oacc[nt][1]*i0 };
        float2 v1 = { oacc[nt][2]*i1, oacc[nt][3]*i1 };
        *(float2*)&out[(b*NL + r0 + gID    )*NC + col] = v0;
        *(float2*)&out[(b*NL + r0 + gID + 8)*NC + col] = v1;
    }
}

// ----------------- conv weight transform: w[co][ci][tap] -> wt[tap][co][ci] -
__global__ __launch_bounds__(256) void wtrans_kernel(
    const float* __restrict__ wq, const float* __restrict__ wk,
    const float* __restrict__ wv)
{
    const float* W = (blockIdx.y == 0) ? wq : (blockIdx.y == 1) ? wk : wv;
    float* dst = g_wt + blockIdx.y * 9*NC*NC;
    const int idx = blockIdx.x * 256 + threadIdx.x;
    const int ci  = idx & 255;
    const int rem = idx >> 8;
    const int co  = rem & 255;
    const int tap = rem >> 8;
    dst[idx] = W[(co*NC + ci)*9 + tap];
}

// --------------------------- BN stats + fold --------------------------------
__global__ __launch_bounds__(256) void stats_partial_kernel()
{
    const float* src = g_cv + (long)blockIdx.y * NT*NC;
    const int c = threadIdx.x;
    float s = 0.f, s2 = 0.f;
    const int t0 = blockIdx.x * (NT/64);
    for (int t = t0; t < t0 + NT/64; t++) {
        float val = src[t*NC + c];
        s += val; s2 += val*val;
    }
    g_part[((blockIdx.y*64 + blockIdx.x)*2 + 0)*NC + c] = s;
    g_part[((blockIdx.y*64 + blockIdx.x)*2 + 1)*NC + c] = s2;
}

__global__ __launch_bounds__(256) void stats_final_kernel(
    const float* __restrict__ gq, const float* __restrict__ bq,
    const float* __restrict__ gk, const float* __restrict__ bk,
    const float* __restrict__ gv, const float* __restrict__ bv)
{
    const int s = blockIdx.x;
    const int c = threadIdx.x;
    float sum = 0.f, sum2 = 0.f;
    for (int i = 0; i < 64; i++) {
        sum  += g_part[((s*64+i)*2 + 0)*NC + c];
        sum2 += g_part[((s*64+i)*2 + 1)*NC + c];
    }
    float mu  = sum  * (1.f/NT);
    float var = sum2 * (1.f/NT) - mu*mu;
    const float* gam = (s == 0) ? gq : (s == 1) ? gk : gv;
    const float* bet = (s == 0) ? bq : (s == 1) ? bk : bv;
    float a  = gam[c] * rsqrtf(var + 1e-5f);
    float bb = bet[c] - mu*a;
    g_ab[(s*2+0)*NC + c] = a;
    g_ab[(s*2+1)*NC + c] = bb;
}

__global__ __launch_bounds__(256) void fold_kernel(
    const float* __restrict__ Wq, const float* __restrict__ Wk,
    const float* __restrict__ Wv)
{
    const int s  = blockIdx.y;
    const int co = blockIdx.x;
    const int c  = threadIdx.x;
    const float* W = (s == 0) ? Wq : (s == 1) ? Wk : Wv;
    float a  = g_ab[(s*2+0)*NC + c];
    float bb = g_ab[(s*2+1)*NC + c];
    float wv = W[co*NC + c];
    g_wf[s*NC*NC + co*NC + c] = wv * a;

    __shared__ float red[256];
    red[c] = wv * bb;
    __syncthreads();
    for (int o = 128; o > 0; o >>= 1) {
        if (c < o) red[c] += red[c + o];
        __syncthreads();
    }
    if (c == 0) g_bf[s*NC + co] = red[0];
}

// ---------------------------------------------------------------------------

extern "C" void kernel_launch(void* const* d_in, const int* in_sizes, int n_in,
                              void* d_out, int out_size)
{
    const float* x        = (const float*)d_in[0];
    const float* y        = (const float*)d_in[1];
    const float* conv_q_w = (const float*)d_in[4];
    const float* bn_q_g   = (const float*)d_in[5];
    const float* bn_q_b   = (const float*)d_in[6];
    const float* conv_k_w = (const float*)d_in[7];
    const float* bn_k_g   = (const float*)d_in[8];
    const float* bn_k_b   = (const float*)d_in[9];
    const float* conv_v_w = (const float*)d_in[10];
    const float* bn_v_g   = (const float*)d_in[11];
    const float* bn_v_b   = (const float*)d_in[12];
    const float* Wq       = (const float*)d_in[13];
    const float* Wk       = (const float*)d_in[14];
    const float* Wv       = (const float*)d_in[15];
    const float* Wo       = (const float*)d_in[16];
    const float* bo       = (const float*)d_in[17];
    float* out = (float*)d_out;

    float *cv, *pr, *ao, *wf, *bf, *wt;
    cudaGetSymbolAddress((void**)&cv, g_cv);
    cudaGetSymbolAddress((void**)&pr, g_pr);
    cudaGetSymbolAddress((void**)&ao, g_ao);
    cudaGetSymbolAddress((void**)&wf, g_wf);
    cudaGetSymbolAddress((void**)&bf, g_bf);
    cudaGetSymbolAddress((void**)&wt, g_wt);

    const int GEMM_SMEM = 4 * 128 * KS * 4;                       // 73728 B
    const int ATTN_SMEM = (2*64*KS + 2*64*VS + 64*PS) * 4;        // 56320 B
    cudaFuncSetAttribute(mma_gemm_kernel,
                         cudaFuncAttributeMaxDynamicSharedMemorySize, GEMM_SMEM);
    cudaFuncSetAttribute(attn_mma_kernel,
                         cudaFuncAttributeMaxDynamicSharedMemorySize, ATTN_SMEM);

    // conv weight layout transform
    wtrans_kernel<<<dim3(9*NC, 3), 256>>>(conv_q_w, conv_k_w, conv_v_w);

    // 3 convs fused: z=0 reads x, z=1/2 read y
    mma_gemm_kernel<<<dim3(NT/128, NC/128, 3), 256, GEMM_SMEM>>>(
        x, y, y, wt, (long)9*NC*NC, nullptr, cv, (long)NT*NC, 1, 0);

    // BN stats -> fold into projection weights
    stats_partial_kernel<<<dim3(64, 3), 256>>>();
    stats_final_kernel<<<3, 256>>>(bn_q_g, bn_q_b, bn_k_g, bn_k_b, bn_v_g, bn_v_b);
    fold_kernel<<<dim3(NC, 3), 256>>>(Wq, Wk, Wv);

    // 3 projections fused (BN folded), split-head output
    mma_gemm_kernel<<<dim3(NT/128, NC/128, 3), 256, GEMM_SMEM>>>(
        cv, cv + (long)NT*NC, cv + (long)2*NT*NC,
        wf, (long)NC*NC, bf, pr, (long)NT*NC, 0, 1);

    // flash attention on tensor cores
    attn_mma_kernel<<<dim3(NB*NH, NL/64), 128, ATTN_SMEM>>>(
        pr, pr + (long)NT*NC, pr + (long)2*NT*NC, ao);

    // output projection
    mma_gemm_kernel<<<dim3(NT/128, NC/128, 1), 256, GEMM_SMEM>>>(
        ao, ao, ao, Wo, 0, bo, out, 0, 0, 0);
}

// round 7
// speedup vs baseline: 3.4828x; 1.0592x over previous
#include <cuda_runtime.h>
#include <math.h>
#include <cstdint>

#define NB 8
#define NL 1024
#define NC 256
#define NH 8
#define HD 32
#define NT (NB*NL)   /* 8192 tokens */

// ------------------------- scratch (device globals) -------------------------
static __device__ float g_xr[NT*NC];       // tf32-rounded x
static __device__ float g_yr[NT*NC];       // tf32-rounded y
static __device__ float g_cv[3*NT*NC];     // conv outputs q/k/v (tf32-rounded)
static __device__ float g_pr[3*NT*NC];     // projected q/k/v [B,H,L,d] (rounded)
static __device__ float g_ao[NT*NC];       // attention output [B,L,C] (rounded)
static __device__ float g_part[3*64*2*NC];
static __device__ float g_ab[3*2*NC];
static __device__ float g_wf[3*NC*NC];     // BN-folded proj weights (rounded)
static __device__ float g_bf[3*NC];
static __device__ float g_wt[3*9*NC*NC];   // conv weights [conv][tap][co][ci] (rounded)
static __device__ float g_wo[NC*NC];       // rounded Wo

// ------------------------------ helpers -------------------------------------
__device__ __forceinline__ uint32_t to_tf32(float f) {
    uint32_t r;
    asm("cvt.rna.tf32.f32 %0, %1;" : "=r"(r) : "f"(f));
    return r;
}
__device__ __forceinline__ float rndf(float f) {
    return __uint_as_float(to_tf32(f));
}
__device__ __forceinline__ uint32_t cvta_s(const void* p) {
    return (uint32_t)__cvta_generic_to_shared(p);
}
__device__ __forceinline__ void cp16(uint32_t d, const void* s, uint32_t sz) {
    asm volatile("cp.async.cg.shared.global [%0], [%1], 16, %2;"
                 :: "r"(d), "l"(s), "r"(sz));
}
#define CP_COMMIT() asm volatile("cp.async.commit_group;")
#define CP_WAIT1()  asm volatile("cp.async.wait_group 1;")
#define CP_WAIT0()  asm volatile("cp.async.wait_group 0;")

__device__ __forceinline__ void mma_tf32(float* c, const uint32_t* a, const uint32_t* b) {
    asm volatile(
        "mma.sync.aligned.m16n8k8.row.col.f32.tf32.tf32.f32 "
        "{%0,%1,%2,%3}, {%4,%5,%6,%7}, {%8,%9}, {%0,%1,%2,%3};"
        : "+f"(c[0]), "+f"(c[1]), "+f"(c[2]), "+f"(c[3])
        : "r"(a[0]), "r"(a[1]), "r"(a[2]), "r"(a[3]), "r"(b[0]), "r"(b[1]));
}
#define U(x) __float_as_uint(x)

// ---------------------------------------------------------------------------
// Implicit 3x3 conv on tensor cores with spatial-halo smem reuse.
// Tile: M=128 tokens (4 image rows x 32 cols) x N=64 co. 8 warps (4m x 2n),
// warp tile 32x32. K-loop: 32 ci-chunks of 8; per chunk all 9 taps off smem.
// A halo: [6 rows][34 cols][ci stride 12], B: [9 taps][64 co][ci stride 12].
// grid (64, 4, 3). Double-buffered cp.async. Output rounded to tf32.
// ---------------------------------------------------------------------------
#define CONV_ASZ 2448   /* 6*34*12 */
#define CONV_BSZ 6912   /* 9*64*12 */
#define CONV_NCH 32     /* 32 chunks x 8 ci = 256 input channels */

__global__ __launch_bounds__(256) void conv_gemm_kernel()
{
    extern __shared__ float sm[];
    float* sA[2] = { sm, sm + CONV_ASZ };
    float* sB[2] = { sm + 2*CONV_ASZ, sm + 2*CONV_ASZ + CONV_BSZ };

    const int z = blockIdx.z;
    const float* Ain = (z == 0) ? g_xr : g_yr;
    const float* Wtz = g_wt + (long)z * 9*NC*NC;
    float* out = g_cv + (long)z * NT*NC;

    const int tid = threadIdx.x;
    const int wid = tid >> 5, lane = tid & 31;
    const int gID = lane >> 2, tq = lane & 3;
    const int wm = (wid >> 1) * 32, wn = (wid & 1) * 32;
    const int m0 = blockIdx.x * 128, n0 = blockIdx.y * 64;
    const int bImg = blockIdx.x >> 3;
    const int r0b  = (blockIdx.x & 7) * 4;

    auto load_stage = [&](int cc, int st) {
        const int ci0 = cc * 8;
        // A halo: 204 cells x 8 ci = 408 16B chunks
        for (int q = tid; q < 408; q += 256) {
            const int cell = q >> 1, half = q & 1;
            const int hr = cell / 34, hc = cell - hr*34;
            const int ir = r0b + hr - 1, ic = hc - 1;
            const bool ok = ((unsigned)ir < 32u) && ((unsigned)ic < 32u);
            const float* src = ok ? &Ain[((bImg<<10) + ir*32 + ic)*NC + ci0 + half*4]
                                  : Ain;
            cp16(cvta_s(&sA[st][cell*12 + half*4]), src, ok ? 16 : 0);
        }
        // B: 9*64 rows x 8 ci = 1152 chunks
        for (int q = tid; q < 1152; q += 256) {
            const int rowc = q >> 1, half = q & 1;
            const int tap = rowc >> 6, co = rowc & 63;
            const float* src = &Wtz[((tap<<8) + n0 + co)*NC + ci0 + half*4];
            cp16(cvta_s(&sB[st][rowc*12 + half*4]), src, 16);
        }
    };

    float acc[2][4][4];
    #pragma unroll
    for (int i = 0; i < 2; i++)
        #pragma unroll
        for (int j = 0; j < 4; j++)
            #pragma unroll
            for (int c = 0; c < 4; c++) acc[i][j][c] = 0.f;

    load_stage(0, 0); CP_COMMIT();

    for (int cc = 0; cc < CONV_NCH; cc++) {
        const int cur = cc & 1;
        if (cc + 1 < CONV_NCH) { load_stage(cc + 1, cur ^ 1); CP_COMMIT(); CP_WAIT1(); }
        else                   { CP_WAIT0(); }
        __syncthreads();
        const float* a = sA[cur];
        const float* b = sB[cur];

        #pragma unroll
        for (int tap = 0; tap < 9; tap++) {
            const int d3 = tap / 3, m3 = tap - d3*3;
            uint32_t bf2[4][2];
            #pragma unroll
            for (int nt = 0; nt < 4; nt++) {
                const float* pb = &b[(tap*64 + wn + nt*8 + gID)*12 + tq];
                bf2[nt][0] = U(pb[0]); bf2[nt][1] = U(pb[4]);
            }
            #pragma unroll
            for (int mt = 0; mt < 2; mt++) {
                const int base = wm + mt*16;
                const int rA = base >> 5, cA0 = base & 31;
                const float* pa = &a[((rA + d3)*34 + cA0 + gID + m3)*12 + tq];
                uint32_t af[4] = { U(pa[0]), U(pa[96]), U(pa[4]), U(pa[100]) };
                #pragma unroll
                for (int nt = 0; nt < 4; nt++)
                    mma_tf32(acc[mt][nt], af, bf2[nt]);
            }
        }
        __syncthreads();
    }

    #pragma unroll
    for (int mt = 0; mt < 2; mt++) {
        #pragma unroll
        for (int half = 0; half < 2; half++) {
            const int t = m0 + wm + mt*16 + gID + half*8;
            #pragma unroll
            for (int nt = 0; nt < 4; nt++) {
                const int n = n0 + wn + nt*8 + tq*2;
                float2 v = { rndf(acc[mt][nt][half*2 + 0]),
                             rndf(acc[mt][nt][half*2 + 1]) };
                *(float2*)&out[t*NC + n] = v;
            }
        }
    }
}

// ---------------------------------------------------------------------------
// Plain tensor-core GEMM: out[t,n] = sum_k A[t,k]*Bw[n,k] (+bias).
// Tile M=128 x N=64, 8 warps (4m x 2n, warp 32x32), K-chunks of 32.
// Operands pre-rounded to tf32 (no cvt in loop). grid (64, 4, z).
// ---------------------------------------------------------------------------
__global__ __launch_bounds__(256) void gemm_kernel(
    const float* __restrict__ A0, const float* __restrict__ A1,
    const float* __restrict__ A2,
    const float* __restrict__ B0, long bStride,
    const float* __restrict__ bias0, float* __restrict__ out0, long oStride,
    int split, int rnd)
{
    extern __shared__ float sm[];
    float* sA[2] = { sm, sm + 4608 };
    float* sB[2] = { sm + 9216, sm + 9216 + 2304 };

    const int z = blockIdx.z;
    const float* A    = (z == 0) ? A0 : ((z == 1) ? A1 : A2);
    const float* Bw   = B0 + (long)z * bStride;
    const float* bias = bias0 ? (bias0 + z*NC) : nullptr;
    float* out        = out0 + (long)z * oStride;

    const int tid = threadIdx.x;
    const int wid = tid >> 5, lane = tid & 31;
    const int gID = lane >> 2, tq = lane & 3;
    const int wm = (wid >> 1) * 32, wn = (wid & 1) * 32;
    const int m0 = blockIdx.x * 128, n0 = blockIdx.y * 64;

    auto load_stage = [&](int ch, int st) {
        const int k0 = ch * 32;
        #pragma unroll
        for (int u = 0; u < 4; u++) {
            const int q = u*256 + tid, row = q >> 3, c4 = q & 7;
            cp16(cvta_s(&sA[st][row*36 + c4*4]), &A[(m0+row)*NC + k0 + c4*4], 16);
        }
        #pragma unroll
        for (int u = 0; u < 2; u++) {
            const int q = u*256 + tid, row = q >> 3, c4 = q & 7;
            cp16(cvta_s(&sB[st][row*36 + c4*4]), &Bw[(n0+row)*NC + k0 + c4*4], 16);
        }
    };

    float acc[2][4][4];
    #pragma unroll
    for (int i = 0; i < 2; i++)
        #pragma unroll
        for (int j = 0; j < 4; j++)
            #pragma unroll
            for (int c = 0; c < 4; c++) acc[i][j][c] = 0.f;

    load_stage(0, 0); CP_COMMIT();

    for (int ch = 0; ch < 8; ch++) {
        const int cur = ch & 1;
        if (ch + 1 < 8) { load_stage(ch + 1, cur ^ 1); CP_COMMIT(); CP_WAIT1(); }
        else            { CP_WAIT0(); }
        __syncthreads();

        #pragma unroll
        for (int kk = 0; kk < 32; kk += 8) {
            uint32_t bf2[4][2];
            #pragma unroll
            for (int nt = 0; nt < 4; nt++) {
                const float* pb = &sB[cur][(wn + nt*8 + gID)*36 + kk + tq];
                bf2[nt][0] = U(pb[0]); bf2[nt][1] = U(pb[4]);
            }
            #pragma unroll
            for (int mt = 0; mt < 2; mt++) {
                const float* pa = &sA[cur][(wm + mt*16 + gID)*36 + kk + tq];
                uint32_t af[4] = { U(pa[0]), U(pa[8*36]), U(pa[4]), U(pa[8*36+4]) };
                #pragma unroll
                for (int nt = 0; nt < 4; nt++)
                    mma_tf32(acc[mt][nt], af, bf2[nt]);
            }
        }
        __syncthreads();
    }

    #pragma unroll
    for (int mt = 0; mt < 2; mt++) {
        #pragma unroll
        for (int half = 0; half < 2; half++) {
            const int t = m0 + wm + mt*16 + gID + half*8;
            #pragma unroll
            for (int nt = 0; nt < 4; nt++) {
                const int n = n0 + wn + nt*8 + tq*2;
                float v0 = acc[mt][nt][half*2 + 0];
                float v1 = acc[mt][nt][half*2 + 1];
                if (bias) { v0 += bias[n]; v1 += bias[n+1]; }
                if (rnd)  { v0 = rndf(v0); v1 = rndf(v1); }
                float2 v = { v0, v1 };
                if (split) {
                    const int bb = t >> 10, tt = t & 1023;
                    const int h = n >> 5, d = n & 31;
                    *(float2*)&out[((bb*NH + h)*NL + tt)*HD + d] = v;
                } else {
                    *(float2*)&out[t*NC + n] = v;
                }
            }
        }
    }
}

// ---------------------------------------------------------------------------
// Tensor-core flash attention (tf32 mma, fp32 softmax). Operands pre-rounded.
// Block = 128 threads (4 warps x 16 q rows). grid (64 bh, 16 q-tiles).
// P tile is 64x64 -> stride PS=68 (68g+tq ≡ 4g+tq mod 32 -> conflict-free).
// ---------------------------------------------------------------------------
#define KSA 36
#define VS 40
#define PS 68

__global__ __launch_bounds__(128) void attn_mma_kernel(
    const float* __restrict__ Q, const float* __restrict__ K,
    const float* __restrict__ V, float* __restrict__ out)
{
    extern __shared__ float sm[];
    float* sK[2] = { sm, sm + 64*KSA };
    float* sV[2] = { sm + 2*64*KSA, sm + 2*64*KSA + 64*VS };
    float* sP    = sm + 2*64*KSA + 2*64*VS;   // 64 x PS

    const int bh = blockIdx.x, qt = blockIdx.y;
    const int tid = threadIdx.x, w = tid >> 5, lane = tid & 31;
    const int gID = lane >> 2, tq = lane & 3;
    const int r0 = qt*64 + w*16;
    const float* Qb = Q + (long)bh*NL*HD;
    const float* Kb = K + (long)bh*NL*HD;
    const float* Vb = V + (long)bh*NL*HD;

    const float scale = 0.0625f;   // exact power of two: tf32-safe
    uint32_t qf[4][4];
    #pragma unroll
    for (int ks = 0; ks < 4; ks++) {
        qf[ks][0] = U(Qb[(r0+gID  )*HD + ks*8 + tq    ] * scale);
        qf[ks][1] = U(Qb[(r0+gID+8)*HD + ks*8 + tq    ] * scale);
        qf[ks][2] = U(Qb[(r0+gID  )*HD + ks*8 + tq + 4] * scale);
        qf[ks][3] = U(Qb[(r0+gID+8)*HD + ks*8 + tq + 4] * scale);
    }

    float m0 = -1e30f, m1 = -1e30f, l0 = 0.f, l1 = 0.f;
    float oacc[4][4];
    #pragma unroll
    for (int i = 0; i < 4; i++)
        #pragma unroll
        for (int j = 0; j < 4; j++) oacc[i][j] = 0.f;

    auto load_kv = [&](int kt, int st) {
        #pragma unroll
        for (int u = 0; u < 4; u++) {
            const int idx = u*128 + tid, row = idx >> 3, c4 = idx & 7;
            cp16(cvta_s(&sK[st][row*KSA + c4*4]), &Kb[(kt*64 + row)*HD + c4*4], 16);
            cp16(cvta_s(&sV[st][row*VS  + c4*4]), &Vb[(kt*64 + row)*HD + c4*4], 16);
        }
    };

    load_kv(0, 0); CP_COMMIT();

    for (int kt = 0; kt < 16; kt++) {
        const int cur = kt & 1;
        if (kt + 1 < 16) { load_kv(kt + 1, cur ^ 1); CP_COMMIT(); CP_WAIT1(); }
        else             { CP_WAIT0(); }
        __syncthreads();

        // S = Q K^T (16 x 64 per warp)
        float sacc[8][4];
        #pragma unroll
        for (int nt = 0; nt < 8; nt++)
            #pragma unroll
            for (int c = 0; c < 4; c++) sacc[nt][c] = 0.f;
        #pragma unroll
        for (int kk = 0; kk < 4; kk++) {
            #pragma unroll
            for (int nt = 0; nt < 8; nt++) {
                const float* pb = &sK[cur][(nt*8 + gID)*KSA + kk*8 + tq];
                uint32_t b[2] = { U(pb[0]), U(pb[4]) };
                mma_tf32(sacc[nt], qf[kk], b);
            }
        }

        // online softmax
        float mx0 = -1e30f, mx1 = -1e30f;
        #pragma unroll
        for (int nt = 0; nt < 8; nt++) {
            mx0 = fmaxf(mx0, fmaxf(sacc[nt][0], sacc[nt][1]));
            mx1 = fmaxf(mx1, fmaxf(sacc[nt][2], sacc[nt][3]));
        }
        mx0 = fmaxf(mx0, __shfl_xor_sync(~0u, mx0, 1));
        mx0 = fmaxf(mx0, __shfl_xor_sync(~0u, mx0, 2));
        mx1 = fmaxf(mx1, __shfl_xor_sync(~0u, mx1, 1));
        mx1 = fmaxf(mx1, __shfl_xor_sync(~0u, mx1, 2));
        const float mn0 = fmaxf(m0, mx0), mn1 = fmaxf(m1, mx1);
        const float c0 = __expf(m0 - mn0), c1 = __expf(m1 - mn1);

        float s0 = 0.f, s1 = 0.f;
        #pragma unroll
        for (int nt = 0; nt < 8; nt++) {
            float p0 = __expf(sacc[nt][0] - mn0);
            float p1 = __expf(sacc[nt][1] - mn0);
            float p2 = __expf(sacc[nt][2] - mn1);
            float p3 = __expf(sacc[nt][3] - mn1);
            s0 += p0 + p1; s1 += p2 + p3;
            float* pr  = &sP[(w*16 + gID    )*PS + nt*8 + tq*2];
            float* pr2 = &sP[(w*16 + gID + 8)*PS + nt*8 + tq*2];
            pr[0]  = rndf(p0); pr[1]  = rndf(p1);
            pr2[0] = rndf(p2); pr2[1] = rndf(p3);
        }
        s0 += __shfl_xor_sync(~0u, s0, 1); s0 += __shfl_xor_sync(~0u, s0, 2);
        s1 += __shfl_xor_sync(~0u, s1, 1); s1 += __shfl_xor_sync(~0u, s1, 2);
        l0 = l0*c0 + s0; l1 = l1*c1 + s1;
        #pragma unroll
        for (int nt = 0; nt < 4; nt++) {
            oacc[nt][0] *= c0; oacc[nt][1] *= c0;
            oacc[nt][2] *= c1; oacc[nt][3] *= c1;
        }
        m0 = mn0; m1 = mn1;
        __syncwarp();

        // O += P V
        #pragma unroll
        for (int kk = 0; kk < 8; kk++) {
            const float* pb = &sP[(w*16 + gID)*PS + kk*8 + tq];
            uint32_t pa[4] = { U(pb[0]), U(pb[8*PS]), U(pb[4]), U(pb[8*PS + 4]) };
            #pragma unroll
            for (int nt = 0; nt < 4; nt++) {
                uint32_t vb[2] = { U(sV[cur][(kk*8 + tq    )*VS + nt*8 + gID]),
                                   U(sV[cur][(kk*8 + tq + 4)*VS + nt*8 + gID]) };
                mma_tf32(oacc[nt], pa, vb);
            }
        }
        __syncthreads();
    }

    const float i0 = 1.f / l0, i1 = 1.f / l1;
    const int b = bh >> 3, h = bh & 7;
    #pragma unroll
    for (int nt = 0; nt < 4; nt++) {
        const int col = h*HD + nt*8 + tq*2;
        float2 v0 = { rndf(oacc[nt][0]*i0), rndf(oacc[nt][1]*i0) };
        float2 v1 = { rndf(oacc[nt][2]*i1), rndf(oacc[nt][3]*i1) };
        *(float2*)&out[(b*NL + r0 + gID    )*NC + col] = v0;
        *(float2*)&out[(b*NL + r0 + gID + 8)*NC + col] = v1;
    }
}

// ------------------------ small prep / stats kernels ------------------------
__global__ __launch_bounds__(256) void round_xy_kernel(
    const float* __restrict__ x, const float* __restrict__ y)
{
    const float* s = blockIdx.y ? y : x;
    float* d = blockIdx.y ? g_yr : g_xr;
    const int i = (blockIdx.x * 256 + threadIdx.x) * 4;
    float4 v = *(const float4*)(s + i);
    v.x = rndf(v.x); v.y = rndf(v.y); v.z = rndf(v.z); v.w = rndf(v.w);
    *(float4*)(d + i) = v;
}

__global__ __launch_bounds__(256) void round_wo_kernel(const float* __restrict__ Wo)
{
    const int i = (blockIdx.x * 256 + threadIdx.x) * 4;
    float4 v = *(const float4*)(Wo + i);
    v.x = rndf(v.x); v.y = rndf(v.y); v.z = rndf(v.z); v.w = rndf(v.w);
    *(float4*)(g_wo + i) = v;
}

__global__ __launch_bounds__(256) void wtrans_kernel(
    const float* __restrict__ wq, const float* __restrict__ wk,
    const float* __restrict__ wv)
{
    const float* W = (blockIdx.y == 0) ? wq : (blockIdx.y == 1) ? wk : wv;
    float* dst = g_wt + (long)blockIdx.y * 9*NC*NC;
    const int idx = blockIdx.x * 256 + threadIdx.x;
    const int ci  = idx & 255;
    const int rem = idx >> 8;
    const int co  = rem & 255;
    const int tap = rem >> 8;
    dst[idx] = rndf(W[(co*NC + ci)*9 + tap]);
}

__global__ __launch_bounds__(256) void stats_partial_kernel()
{
    const float* src = g_cv + (long)blockIdx.y * NT*NC;
    const int c = threadIdx.x;
    float s = 0.f, s2 = 0.f;
    const int t0 = blockIdx.x * (NT/64);
    #pragma unroll 4
    for (int t = t0; t < t0 + NT/64; t++) {
        float val = src[t*NC + c];
        s += val; s2 += val*val;
    }
    g_part[((blockIdx.y*64 + blockIdx.x)*2 + 0)*NC + c] = s;
    g_part[((blockIdx.y*64 + blockIdx.x)*2 + 1)*NC + c] = s2;
}

__global__ __launch_bounds__(1024) void stats_final_kernel(
    const float* __restrict__ gq, const float* __restrict__ bq,
    const float* __restrict__ gk, const float* __restrict__ bk,
    const float* __restrict__ gv, const float* __restrict__ bv)
{
    const int s = blockIdx.x;
    const int c = threadIdx.x & 255;
    const int seg = threadIdx.x >> 8;
    float sum = 0.f, sum2 = 0.f;
    #pragma unroll
    for (int i = seg*16; i < seg*16 + 16; i++) {
        sum  += g_part[((s*64+i)*2 + 0)*NC + c];
        sum2 += g_part[((s*64+i)*2 + 1)*NC + c];
    }
    __shared__ float red[8][256];
    red[seg][c] = sum; red[4+seg][c] = sum2;
    __syncthreads();
    if (seg == 0) {
        sum  = red[0][c] + red[1][c] + red[2][c] + red[3][c];
        sum2 = red[4][c] + red[5][c] + red[6][c] + red[7][c];
        float mu  = sum  * (1.f/NT);
        float var = sum2 * (1.f/NT) - mu*mu;
        const float* gam = (s == 0) ? gq : (s == 1) ? gk : gv;
        const float* bet = (s == 0) ? bq : (s == 1) ? bk : bv;
        float a  = gam[c] * rsqrtf(var + 1e-5f);
        float bb = bet[c] - mu*a;
        g_ab[(s*2+0)*NC + c] = a;
        g_ab[(s*2+1)*NC + c] = bb;
    }
}

__global__ __launch_bounds__(256) void fold_kernel(
    const float* __restrict__ Wq, const float* __restrict__ Wk,
    const float* __restrict__ Wv)
{
    const int s  = blockIdx.y;
    const int co = blockIdx.x;
    const int c  = threadIdx.x;
    const float* W = (s == 0) ? Wq : (s == 1) ? Wk : Wv;
    float a  = g_ab[(s*2+0)*NC + c];
    float bb = g_ab[(s*2+1)*NC + c];
    float wv = W[co*NC + c];
    g_wf[s*NC*NC + co*NC + c] = rndf(wv * a);

    __shared__ float red[256];
    red[c] = wv * bb;
    __syncthreads();
    for (int o = 128; o > 0; o >>= 1) {
        if (c < o) red[c] += red[c + o];
        __syncthreads();
    }
    if (c == 0) g_bf[s*NC + co] = red[0];
}

// ---------------------------------------------------------------------------

extern "C" void kernel_launch(void* const* d_in, const int* in_sizes, int n_in,
                              void* d_out, int out_size)
{
    const float* x        = (const float*)d_in[0];
    const float* y        = (const float*)d_in[1];
    const float* conv_q_w = (const float*)d_in[4];
    const float* bn_q_g   = (const float*)d_in[5];
    const float* bn_q_b   = (const float*)d_in[6];
    const float* conv_k_w = (const float*)d_in[7];
    const float* bn_k_g   = (const float*)d_in[8];
    const float* bn_k_b   = (const float*)d_in[9];
    const float* conv_v_w = (const float*)d_in[10];
    const float* bn_v_g   = (const float*)d_in[11];
    const float* bn_v_b   = (const float*)d_in[12];
    const float* Wq       = (const float*)d_in[13];
    const float* Wk       = (const float*)d_in[14];
    const float* Wv       = (const float*)d_in[15];
    const float* Wo       = (const float*)d_in[16];
    const float* bo       = (const float*)d_in[17];
    float* out = (float*)d_out;

    float *cv, *pr, *ao, *wf, *bf, *wo;
    cudaGetSymbolAddress((void**)&cv, g_cv);
    cudaGetSymbolAddress((void**)&pr, g_pr);
    cudaGetSymbolAddress((void**)&ao, g_ao);
    cudaGetSymbolAddress((void**)&wf, g_wf);
    cudaGetSymbolAddress((void**)&bf, g_bf);
    cudaGetSymbolAddress((void**)&wo, g_wo);

    const int CONV_SMEM = (2*CONV_ASZ + 2*CONV_BSZ) * 4;          // 74880 B
    const int GEMM_SMEM = (2*4608 + 2*2304) * 4;                  // 55296 B
    const int ATTN_SMEM = (2*64*KSA + 2*64*VS + 64*PS) * 4;       // 56320 B
    cudaFuncSetAttribute(conv_gemm_kernel,
                         cudaFuncAttributeMaxDynamicSharedMemorySize, CONV_SMEM);
    cudaFuncSetAttribute(gemm_kernel,
                         cudaFuncAttributeMaxDynamicSharedMemorySize, GEMM_SMEM);
    cudaFuncSetAttribute(attn_mma_kernel,
                         cudaFuncAttributeMaxDynamicSharedMemorySize, ATTN_SMEM);

    // operand pre-rounding + weight layout
    round_xy_kernel<<<dim3(NT*NC/1024, 2), 256>>>(x, y);
    wtrans_kernel<<<dim3(9*NC, 3), 256>>>(conv_q_w, conv_k_w, conv_v_w);
    round_wo_kernel<<<NC*NC/1024, 256>>>(Wo);

    // 3 convs, halo implicit GEMM (full 256-channel reduction)
    conv_gemm_kernel<<<dim3(NT/128, NC/64, 3), 256, CONV_SMEM>>>();

    // BN stats -> fold into projection weights
    stats_partial_kernel<<<dim3(64, 3), 256>>>();
    stats_final_kernel<<<3, 1024>>>(bn_q_g, bn_q_b, bn_k_g, bn_k_b, bn_v_g, bn_v_b);
    fold_kernel<<<dim3(NC, 3), 256>>>(Wq, Wk, Wv);

    // 3 projections (BN folded), split-head rounded output
    gemm_kernel<<<dim3(NT/128, NC/64, 3), 256, GEMM_SMEM>>>(
        cv, cv + (long)NT*NC, cv + (long)2*NT*NC,
        wf, (long)NC*NC, bf, pr, (long)NT*NC, 1, 1);

    // flash attention on tensor cores
    attn_mma_kernel<<<dim3(NB*NH, NL/64), 128, ATTN_SMEM>>>(
        pr, pr + (long)NT*NC, pr + (long)2*NT*NC, ao);

    // output projection (fp32 output, no rounding)
    gemm_kernel<<<dim3(NT/128, NC/64, 1), 256, GEMM_SMEM>>>(
        ao, ao, ao, wo, 0, bo, out, 0, 0, 0);
}

// round 9
// speedup vs baseline: 3.7464x; 1.0757x over previous
#include <cuda_runtime.h>
#include <math.h>
#include <cstdint>

#define NB 8
#define NL 1024
#define NC 256
#define NH 8
#define HD 32
#define NT (NB*NL)   /* 8192 tokens */

// ------------------------- scratch (device globals) -------------------------
static __device__ float g_xr[NT*NC];       // tf32-rounded x, pair-permuted ci
static __device__ float g_yr[NT*NC];       // tf32-rounded y, pair-permuted ci
static __device__ float g_cv[3*NT*NC];     // conv outputs q/k/v (natural order)
static __device__ float g_pr[3*NT*NC];     // projected q/k/v [B,H,L,d]
static __device__ float g_ao[NT*NC];       // attention output [B,L,C]
static __device__ float g_part[3*64*2*NC];
static __device__ float g_ab[3*2*NC];
static __device__ float g_wf[3*NC*NC];     // BN-folded proj weights (rounded)
static __device__ float g_bf[3*NC];
static __device__ float g_wt[3*9*NC*NC];   // conv w [conv][tap][co][ci-permuted]
static __device__ float g_wo[NC*NC];       // rounded Wo

// ------------------------------ helpers -------------------------------------
__device__ __forceinline__ uint32_t to_tf32(float f) {
    uint32_t r;
    asm("cvt.rna.tf32.f32 %0, %1;" : "=r"(r) : "f"(f));
    return r;
}
__device__ __forceinline__ float rndf(float f) {
    return __uint_as_float(to_tf32(f));
}
__device__ __forceinline__ uint32_t cvta_s(const void* p) {
    return (uint32_t)__cvta_generic_to_shared(p);
}
__device__ __forceinline__ void cp16(uint32_t d, const void* s, uint32_t sz) {
    asm volatile("cp.async.cg.shared.global [%0], [%1], 16, %2;"
                 :: "r"(d), "l"(s), "r"(sz));
}
#define CP_COMMIT() asm volatile("cp.async.commit_group;")
#define CP_WAIT1()  asm volatile("cp.async.wait_group 1;")
#define CP_WAIT0()  asm volatile("cp.async.wait_group 0;")

__device__ __forceinline__ void mma_tf32(float* c, const uint32_t* a, const uint32_t* b) {
    asm volatile(
        "mma.sync.aligned.m16n8k8.row.col.f32.tf32.tf32.f32 "
        "{%0,%1,%2,%3}, {%4,%5,%6,%7}, {%8,%9}, {%0,%1,%2,%3};"
        : "+f"(c[0]), "+f"(c[1]), "+f"(c[2]), "+f"(c[3])
        : "r"(a[0]), "r"(a[1]), "r"(a[2]), "r"(a[3]), "r"(b[0]), "r"(b[1]));
}
#define U(x) __float_as_uint(x)

// pair-permutation within each 8-channel group: storage j holds orig perm(j)
// perm: 0->0 1->4 2->1 3->5 4->2 5->6 6->3 7->7
__device__ __forceinline__ int perm8(int j) { return ((j & 1) << 2) | (j >> 1); }

// ---------------------------------------------------------------------------
// Implicit 3x3 conv on tensor cores, halo smem reuse + pair-permuted ci.
// Tile: M=128 tokens (4 image rows x 32 cols) x N=64 co. 8 warps (4m x 2n),
// warp tile 32x32. K-loop: 32 ci-chunks of 8; per chunk all 9 taps off smem.
// A halo: [6 rows][34 cols][8 ci], B: [9 taps][64 co][8 ci]; stride 8, no pad
// (LDS.64 pattern 8*gID+2tq is conflict-free). grid (64, 4, 3).
// ---------------------------------------------------------------------------
#define CONV_ASZ 1632   /* 6*34*8 */
#define CONV_BSZ 4608   /* 9*64*8 */
#define CONV_NCH 32     /* 32 chunks x 8 ci = 256 input channels */

__global__ __launch_bounds__(256, 3) void conv_gemm_kernel()
{
    extern __shared__ float sm[];
    float* sA[2] = { sm, sm + CONV_ASZ };
    float* sB[2] = { sm + 2*CONV_ASZ, sm + 2*CONV_ASZ + CONV_BSZ };

    const int z = blockIdx.z;
    const float* Ain = (z == 0) ? g_xr : g_yr;
    const float* Wtz = g_wt + (long)z * 9*NC*NC;
    float* out = g_cv + (long)z * NT*NC;

    const int tid = threadIdx.x;
    const int wid = tid >> 5, lane = tid & 31;
    const int gID = lane >> 2, tq = lane & 3;
    const int wm = (wid >> 1) * 32, wn = (wid & 1) * 32;
    const int m0 = blockIdx.x * 128, n0 = blockIdx.y * 64;
    const int bImg = blockIdx.x >> 3;
    const int r0b  = (blockIdx.x & 7) * 4;

    auto load_stage = [&](int cc, int st) {
        const int ci0 = cc * 8;
        // A halo: 204 cells x 8 ci = 408 16B chunks
        for (int q = tid; q < 408; q += 256) {
            const int cell = q >> 1, half = q & 1;
            const int hr = cell / 34, hc = cell - hr*34;
            const int ir = r0b + hr - 1, ic = hc - 1;
            const bool ok = ((unsigned)ir < 32u) && ((unsigned)ic < 32u);
            const float* src = ok ? &Ain[((bImg<<10) + ir*32 + ic)*NC + ci0 + half*4]
                                  : Ain;
            cp16(cvta_s(&sA[st][cell*8 + half*4]), src, ok ? 16 : 0);
        }
        // B: 9*64 rows x 8 ci = 1152 chunks
        for (int q = tid; q < 1152; q += 256) {
            const int rowc = q >> 1, half = q & 1;
            const int tap = rowc >> 6, co = rowc & 63;
            const float* src = &Wtz[((tap<<8) + n0 + co)*NC + ci0 + half*4];
            cp16(cvta_s(&sB[st][rowc*8 + half*4]), src, 16);
        }
    };

    float acc[2][4][4];
    #pragma unroll
    for (int i = 0; i < 2; i++)
        #pragma unroll
        for (int j = 0; j < 4; j++)
            #pragma unroll
            for (int c = 0; c < 4; c++) acc[i][j][c] = 0.f;

    load_stage(0, 0); CP_COMMIT();

    for (int cc = 0; cc < CONV_NCH; cc++) {
        const int cur = cc & 1;
        if (cc + 1 < CONV_NCH) { load_stage(cc + 1, cur ^ 1); CP_COMMIT(); CP_WAIT1(); }
        else                   { CP_WAIT0(); }
        __syncthreads();
        const float* a = sA[cur];
        const float* b = sB[cur];

        #pragma unroll
        for (int tap = 0; tap < 9; tap++) {
            const int d3 = tap / 3, m3 = tap - d3*3;
            uint32_t bf2[4][2];
            #pragma unroll
            for (int nt = 0; nt < 4; nt++) {
                // one LDS.64: (orig tq, orig tq+4)
                const float2 bv = *(const float2*)&b[(tap*64 + wn + nt*8 + gID)*8 + 2*tq];
                bf2[nt][0] = U(bv.x); bf2[nt][1] = U(bv.y);
            }
            #pragma unroll
            for (int mt = 0; mt < 2; mt++) {
                const int base = wm + mt*16;
                const int rA = base >> 5, cA0 = base & 31;
                const int cell = (rA + d3)*34 + cA0 + gID + m3;
                const float2 a01 = *(const float2*)&a[cell*8 + 2*tq];        // rows gID
                const float2 a23 = *(const float2*)&a[(cell + 8)*8 + 2*tq];  // rows gID+8
                uint32_t af[4] = { U(a01.x), U(a23.x), U(a01.y), U(a23.y) };
                #pragma unroll
                for (int nt = 0; nt < 4; nt++)
                    mma_tf32(acc[mt][nt], af, bf2[nt]);
            }
        }
        __syncthreads();
    }

    #pragma unroll
    for (int mt = 0; mt < 2; mt++) {
        #pragma unroll
        for (int half = 0; half < 2; half++) {
            const int t = m0 + wm + mt*16 + gID + half*8;
            #pragma unroll
            for (int nt = 0; nt < 4; nt++) {
                const int n = n0 + wn + nt*8 + tq*2;
                float2 v = { rndf(acc[mt][nt][half*2 + 0]),
                             rndf(acc[mt][nt][half*2 + 1]) };
                *(float2*)&out[t*NC + n] = v;
            }
        }
    }
}

// ---------------------------------------------------------------------------
// Plain tensor-core GEMM: out[t,n] = sum_k A[t,k]*Bw[n,k] (+bias).
// Tile M=128 x N=64, 8 warps (4m x 2n, warp 32x32), K-chunks of 32.
// Operands pre-rounded to tf32. grid (64, 4, z).
// ---------------------------------------------------------------------------
__global__ __launch_bounds__(256) void gemm_kernel(
    const float* __restrict__ A0, const float* __restrict__ A1,
    const float* __restrict__ A2,
    const float* __restrict__ B0, long bStride,
    const float* __restrict__ bias0, float* __restrict__ out0, long oStride,
    int split, int rnd)
{
    extern __shared__ float sm[];
    float* sA[2] = { sm, sm + 4608 };
    float* sB[2] = { sm + 9216, sm + 9216 + 2304 };

    const int z = blockIdx.z;
    const float* A    = (z == 0) ? A0 : ((z == 1) ? A1 : A2);
    const float* Bw   = B0 + (long)z * bStride;
    const float* bias = bias0 ? (bias0 + z*NC) : nullptr;
    float* out        = out0 + (long)z * oStride;

    const int tid = threadIdx.x;
    const int wid = tid >> 5, lane = tid & 31;
    const int gID = lane >> 2, tq = lane & 3;
    const int wm = (wid >> 1) * 32, wn = (wid & 1) * 32;
    const int m0 = blockIdx.x * 128, n0 = blockIdx.y * 64;

    auto load_stage = [&](int ch, int st) {
        const int k0 = ch * 32;
        #pragma unroll
        for (int u = 0; u < 4; u++) {
            const int q = u*256 + tid, row = q >> 3, c4 = q & 7;
            cp16(cvta_s(&sA[st][row*36 + c4*4]), &A[(m0+row)*NC + k0 + c4*4], 16);
        }
        #pragma unroll
        for (int u = 0; u < 2; u++) {
            const int q = u*256 + tid, row = q >> 3, c4 = q & 7;
            cp16(cvta_s(&sB[st][row*36 + c4*4]), &Bw[(n0+row)*NC + k0 + c4*4], 16);
        }
    };

    float acc[2][4][4];
    #pragma unroll
    for (int i = 0; i < 2; i++)
        #pragma unroll
        for (int j = 0; j < 4; j++)
            #pragma unroll
            for (int c = 0; c < 4; c++) acc[i][j][c] = 0.f;

    load_stage(0, 0); CP_COMMIT();

    for (int ch = 0; ch < 8; ch++) {
        const int cur = ch & 1;
        if (ch + 1 < 8) { load_stage(ch + 1, cur ^ 1); CP_COMMIT(); CP_WAIT1(); }
        else            { CP_WAIT0(); }
        __syncthreads();

        #pragma unroll
        for (int kk = 0; kk < 32; kk += 8) {
            uint32_t bf2[4][2];
            #pragma unroll
            for (int nt = 0; nt < 4; nt++) {
                const float* pb = &sB[cur][(wn + nt*8 + gID)*36 + kk + tq];
                bf2[nt][0] = U(pb[0]); bf2[nt][1] = U(pb[4]);
            }
            #pragma unroll
            for (int mt = 0; mt < 2; mt++) {
                const float* pa = &sA[cur][(wm + mt*16 + gID)*36 + kk + tq];
                uint32_t af[4] = { U(pa[0]), U(pa[8*36]), U(pa[4]), U(pa[8*36+4]) };
                #pragma unroll
                for (int nt = 0; nt < 4; nt++)
                    mma_tf32(acc[mt][nt], af, bf2[nt]);
            }
        }
        __syncthreads();
    }

    #pragma unroll
    for (int mt = 0; mt < 2; mt++) {
        #pragma unroll
        for (int half = 0; half < 2; half++) {
            const int t = m0 + wm + mt*16 + gID + half*8;
            #pragma unroll
            for (int nt = 0; nt < 4; nt++) {
                const int n = n0 + wn + nt*8 + tq*2;
                float v0 = acc[mt][nt][half*2 + 0];
                float v1 = acc[mt][nt][half*2 + 1];
                if (bias) { v0 += bias[n]; v1 += bias[n+1]; }
                if (rnd)  { v0 = rndf(v0); v1 = rndf(v1); }
                float2 v = { v0, v1 };
                if (split) {
                    const int bb = t >> 10, tt = t & 1023;
                    const int h = n >> 5, d = n & 31;
                    *(float2*)&out[((bb*NH + h)*NL + tt)*HD + d] = v;
                } else {
                    *(float2*)&out[t*NC + n] = v;
                }
            }
        }
    }
}

// ---------------------------------------------------------------------------
// Tensor-core flash attention (tf32 mma, fp32 softmax). Operands pre-rounded.
// Block = 128 threads (4 warps x 16 q rows). grid (64 bh, 16 q-tiles).
// ---------------------------------------------------------------------------
#define KSA 36
#define VS 40
#define PS 68

__global__ __launch_bounds__(128) void attn_mma_kernel(
    const float* __restrict__ Q, const float* __restrict__ K,
    const float* __restrict__ V, float* __restrict__ out)
{
    extern __shared__ float sm[];
    float* sK[2] = { sm, sm + 64*KSA };
    float* sV[2] = { sm + 2*64*KSA, sm + 2*64*KSA + 64*VS };
    float* sP    = sm + 2*64*KSA + 2*64*VS;   // 64 x PS

    const int bh = blockIdx.x, qt = blockIdx.y;
    const int tid = threadIdx.x, w = tid >> 5, lane = tid & 31;
    const int gID = lane >> 2, tq = lane & 3;
    const int r0 = qt*64 + w*16;
    const float* Qb = Q + (long)bh*NL*HD;
    const float* Kb = K + (long)bh*NL*HD;
    const float* Vb = V + (long)bh*NL*HD;

    const float scale = 0.0625f;   // exact power of two: tf32-safe
    uint32_t qf[4][4];
    #pragma unroll
    for (int ks = 0; ks < 4; ks++) {
        qf[ks][0] = U(Qb[(r0+gID  )*HD + ks*8 + tq    ] * scale);
        qf[ks][1] = U(Qb[(r0+gID+8)*HD + ks*8 + tq    ] * scale);
        qf[ks][2] = U(Qb[(r0+gID  )*HD + ks*8 + tq + 4] * scale);
        qf[ks][3] = U(Qb[(r0+gID+8)*HD + ks*8 + tq + 4] * scale);
    }

    float m0 = -1e30f, m1 = -1e30f, l0 = 0.f, l1 = 0.f;
    float oacc[4][4];
    #pragma unroll
    for (int i = 0; i < 4; i++)
        #pragma unroll
        for (int j = 0; j < 4; j++) oacc[i][j] = 0.f;

    auto load_kv = [&](int kt, int st) {
        #pragma unroll
        for (int u = 0; u < 4; u++) {
            const int idx = u*128 + tid, row = idx >> 3, c4 = idx & 7;
            cp16(cvta_s(&sK[st][row*KSA + c4*4]), &Kb[(kt*64 + row)*HD + c4*4], 16);
            cp16(cvta_s(&sV[st][row*VS  + c4*4]), &Vb[(kt*64 + row)*HD + c4*4], 16);
        }
    };

    load_kv(0, 0); CP_COMMIT();

    for (int kt = 0; kt < 16; kt++) {
        const int cur = kt & 1;
        if (kt + 1 < 16) { load_kv(kt + 1, cur ^ 1); CP_COMMIT(); CP_WAIT1(); }
        else             { CP_WAIT0(); }
        __syncthreads();

        // S = Q K^T (16 x 64 per warp)
        float sacc[8][4];
        #pragma unroll
        for (int nt = 0; nt < 8; nt++)
            #pragma unroll
            for (int c = 0; c < 4; c++) sacc[nt][c] = 0.f;
        #pragma unroll
        for (int kk = 0; kk < 4; kk++) {
            #pragma unroll
            for (int nt = 0; nt < 8; nt++) {
                const float* pb = &sK[cur][(nt*8 + gID)*KSA + kk*8 + tq];
                uint32_t b[2] = { U(pb[0]), U(pb[4]) };
                mma_tf32(sacc[nt], qf[kk], b);
            }
        }

        // online softmax
        float mx0 = -1e30f, mx1 = -1e30f;
        #pragma unroll
        for (int nt = 0; nt < 8; nt++) {
            mx0 = fmaxf(mx0, fmaxf(sacc[nt][0], sacc[nt][1]));
            mx1 = fmaxf(mx1, fmaxf(sacc[nt][2], sacc[nt][3]));
        }
        mx0 = fmaxf(mx0, __shfl_xor_sync(~0u, mx0, 1));
        mx0 = fmaxf(mx0, __shfl_xor_sync(~0u, mx0, 2));
        mx1 = fmaxf(mx1, __shfl_xor_sync(~0u, mx1, 1));
        mx1 = fmaxf(mx1, __shfl_xor_sync(~0u, mx1, 2));
        const float mn0 = fmaxf(m0, mx0), mn1 = fmaxf(m1, mx1);
        const float c0 = __expf(m0 - mn0), c1 = __expf(m1 - mn1);

        float s0 = 0.f, s1 = 0.f;
        #pragma unroll
        for (int nt = 0; nt < 8; nt++) {
            float p0 = __expf(sacc[nt][0] - mn0);
            float p1 = __expf(sacc[nt][1] - mn0);
            float p2 = __expf(sacc[nt][2] - mn1);
            float p3 = __expf(sacc[nt][3] - mn1);
            s0 += p0 + p1; s1 += p2 + p3;
            float* pr  = &sP[(w*16 + gID    )*PS + nt*8 + tq*2];
            float* pr2 = &sP[(w*16 + gID + 8)*PS + nt*8 + tq*2];
            pr[0]  = rndf(p0); pr[1]  = rndf(p1);
            pr2[0] = rndf(p2); pr2[1] = rndf(p3);
        }
        s0 += __shfl_xor_sync(~0u, s0, 1); s0 += __shfl_xor_sync(~0u, s0, 2);
        s1 += __shfl_xor_sync(~0u, s1, 1); s1 += __shfl_xor_sync(~0u, s1, 2);
        l0 = l0*c0 + s0; l1 = l1*c1 + s1;
        #pragma unroll
        for (int nt = 0; nt < 4; nt++) {
            oacc[nt][0] *= c0; oacc[nt][1] *= c0;
            oacc[nt][2] *= c1; oacc[nt][3] *= c1;
        }
        m0 = mn0; m1 = mn1;
        __syncwarp();

        // O += P V
        #pragma unroll
        for (int kk = 0; kk < 8; kk++) {
            const float* pb = &sP[(w*16 + gID)*PS + kk*8 + tq];
            uint32_t pa[4] = { U(pb[0]), U(pb[8*PS]), U(pb[4]), U(pb[8*PS + 4]) };
            #pragma unroll
            for (int nt = 0; nt < 4; nt++) {
                uint32_t vb[2] = { U(sV[cur][(kk*8 + tq    )*VS + nt*8 + gID]),
                                   U(sV[cur][(kk*8 + tq + 4)*VS + nt*8 + gID]) };
                mma_tf32(oacc[nt], pa, vb);
            }
        }
        __syncthreads();
    }

    const float i0 = 1.f / l0, i1 = 1.f / l1;
    const int b = bh >> 3, h = bh & 7;
    #pragma unroll
    for (int nt = 0; nt < 4; nt++) {
        const int col = h*HD + nt*8 + tq*2;
        float2 v0 = { rndf(oacc[nt][0]*i0), rndf(oacc[nt][1]*i0) };
        float2 v1 = { rndf(oacc[nt][2]*i1), rndf(oacc[nt][3]*i1) };
        *(float2*)&out[(b*NL + r0 + gID    )*NC + col] = v0;
        *(float2*)&out[(b*NL + r0 + gID + 8)*NC + col] = v1;
    }
}

// ------------------------ small prep / stats kernels ------------------------
// x/y: tf32-round + pair-permute channels within 8-groups
__global__ __launch_bounds__(256) void round_xy_kernel(
    const float* __restrict__ x, const float* __restrict__ y)
{
    const float* s = blockIdx.y ? y : x;
    float* d = blockIdx.y ? g_yr : g_xr;
    const int i = (blockIdx.x * 256 + threadIdx.x) * 4;
    const int base = i & ~7;       // 8-group start (i is a multiple of 4)
    const int j0 = i & 7;          // 0 or 4
    float4 v;
    v.x = rndf(s[base + perm8(j0 + 0)]);
    v.y = rndf(s[base + perm8(j0 + 1)]);
    v.z = rndf(s[base + perm8(j0 + 2)]);
    v.w = rndf(s[base + perm8(j0 + 3)]);
    *(float4*)(d + i) = v;
}

__global__ __launch_bounds__(256) void round_wo_kernel(const float* __restrict__ Wo)
{
    const int i = (blockIdx.x * 256 + threadIdx.x) * 4;
    float4 v = *(const float4*)(Wo + i);
    v.x = rndf(v.x); v.y = rndf(v.y); v.z = rndf(v.z); v.w = rndf(v.w);
    *(float4*)(g_wo + i) = v;
}

// conv weights -> [conv][tap][co][ci], ci pair-permuted to match g_xr/g_yr
__global__ __launch_bounds__(256) void wtrans_kernel(
    const float* __restrict__ wq, const float* __restrict__ wk,
    const float* __restrict__ wv)
{
    const float* W = (blockIdx.y == 0) ? wq : (blockIdx.y == 1) ? wk : wv;
    float* dst = g_wt + (long)blockIdx.y * 9*NC*NC;
    const int idx = blockIdx.x * 256 + threadIdx.x;
    const int ci  = idx & 255;
    const int rem = idx >> 8;
    const int co  = rem & 255;
    const int tap = rem >> 8;
    const int orig_ci = (ci & ~7) + perm8(ci & 7);
    dst[idx] = rndf(W[(co*NC + orig_ci)*9 + tap]);
}

__global__ __launch_bounds__(256) void stats_partial_kernel()
{
    const float* src = g_cv + (long)blockIdx.y * NT*NC;
    const int c = threadIdx.x;
    float s = 0.f, s2 = 0.f;
    const int t0 = blockIdx.x * (NT/64);
    #pragma unroll 4
    for (int t = t0; t < t0 + NT/64; t++) {
        float val = src[t*NC + c];
        s += val; s2 += val*val;
    }
    g_part[((blockIdx.y*64 + blockIdx.x)*2 + 0)*NC + c] = s;
    g_part[((blockIdx.y*64 + blockIdx.x)*2 + 1)*NC + c] = s2;
}

__global__ __launch_bounds__(1024) void stats_final_kernel(
    const float* __restrict__ gq, const float* __restrict__ bq,
    const float* __restrict__ gk, const float* __restrict__ bk,
    const float* __restrict__ gv, const float* __restrict__ bv)
{
    const int s = blockIdx.x;
    const int c = threadIdx.x & 255;
    const int seg = threadIdx.x >> 8;
    float sum = 0.f, sum2 = 0.f;
    #pragma unroll
    for (int i = seg*16; i < seg*16 + 16; i++) {
        sum  += g_part[((s*64+i)*2 + 0)*NC + c];
        sum2 += g_part[((s*64+i)*2 + 1)*NC + c];
    }
    __shared__ float red[8][256];
    red[seg][c] = sum; red[4+seg][c] = sum2;
    __syncthreads();
    if (seg == 0) {
        sum  = red[0][c] + red[1][c] + red[2][c] + red[3][c];
        sum2 = red[4][c] + red[5][c] + red[6][c] + red[7][c];
        float mu  = sum  * (1.f/NT);
        float var = sum2 * (1.f/NT) - mu*mu;
        const float* gam = (s == 0) ? gq : (s == 1) ? gk : gv;
        const float* bet = (s == 0) ? bq : (s == 1) ? bk : bv;
        float a  = gam[c] * rsqrtf(var + 1e-5f);
        float bb = bet[c] - mu*a;
        g_ab[(s*2+0)*NC + c] = a;
        g_ab[(s*2+1)*NC + c] = bb;
    }
}

__global__ __launch_bounds__(256) void fold_kernel(
    const float* __restrict__ Wq, const float* __restrict__ Wk,
    const float* __restrict__ Wv)
{
    const int s  = blockIdx.y;
    const int co = blockIdx.x;
    const int c  = threadIdx.x;
    const float* W = (s == 0) ? Wq : (s == 1) ? Wk : Wv;
    float a  = g_ab[(s*2+0)*NC + c];
    float bb = g_ab[(s*2+1)*NC + c];
    float wv = W[co*NC + c];
    g_wf[s*NC*NC + co*NC + c] = rndf(wv * a);

    __shared__ float red[256];
    red[c] = wv * bb;
    __syncthreads();
    for (int o = 128; o > 0; o >>= 1) {
        if (c < o) red[c] += red[c + o];
        __syncthreads();
    }
    if (c == 0) g_bf[s*NC + co] = red[0];
}

// ---------------------------------------------------------------------------

extern "C" void kernel_launch(void* const* d_in, const int* in_sizes, int n_in,
                              void* d_out, int out_size)
{
    const float* x        = (const float*)d_in[0];
    const float* y        = (const float*)d_in[1];
    const float* conv_q_w = (const float*)d_in[4];
    const float* bn_q_g   = (const float*)d_in[5];
    const float* bn_q_b   = (const float*)d_in[6];
    const float* conv_k_w = (const float*)d_in[7];
    const float* bn_k_g   = (const float*)d_in[8];
    const float* bn_k_b   = (const float*)d_in[9];
    const float* conv_v_w = (const float*)d_in[10];
    const float* bn_v_g   = (const float*)d_in[11];
    const float* bn_v_b   = (const float*)d_in[12];
    const float* Wq       = (const float*)d_in[13];
    const float* Wk       = (const float*)d_in[14];
    const float* Wv       = (const float*)d_in[15];
    const float* Wo       = (const float*)d_in[16];
    const float* bo       = (const float*)d_in[17];
    float* out = (float*)d_out;

    float *cv, *pr, *ao, *wf, *bf, *wo;
    cudaGetSymbolAddress((void**)&cv, g_cv);
    cudaGetSymbolAddress((void**)&pr, g_pr);
    cudaGetSymbolAddress((void**)&ao, g_ao);
    cudaGetSymbolAddress((void**)&wf, g_wf);
    cudaGetSymbolAddress((void**)&bf, g_bf);
    cudaGetSymbolAddress((void**)&wo, g_wo);

    const int CONV_SMEM = (2*CONV_ASZ + 2*CONV_BSZ) * 4;          // 49920 B
    const int GEMM_SMEM = (2*4608 + 2*2304) * 4;                  // 55296 B
    const int ATTN_SMEM = (2*64*KSA + 2*64*VS + 64*PS) * 4;       // 56320 B
    cudaFuncSetAttribute(conv_gemm_kernel,
                         cudaFuncAttributeMaxDynamicSharedMemorySize, CONV_SMEM);
    cudaFuncSetAttribute(gemm_kernel,
                         cudaFuncAttributeMaxDynamicSharedMemorySize, GEMM_SMEM);
    cudaFuncSetAttribute(attn_mma_kernel,
                         cudaFuncAttributeMaxDynamicSharedMemorySize, ATTN_SMEM);

    // operand pre-rounding + permuted weight layout
    round_xy_kernel<<<dim3(NT*NC/1024, 2), 256>>>(x, y);
    wtrans_kernel<<<dim3(9*NC, 3), 256>>>(conv_q_w, conv_k_w, conv_v_w);
    round_wo_kernel<<<NC*NC/1024, 256>>>(Wo);

    // 3 convs, halo implicit GEMM (full 256-channel reduction)
    conv_gemm_kernel<<<dim3(NT/128, NC/64, 3), 256, CONV_SMEM>>>();

    // BN stats -> fold into projection weights
    stats_partial_kernel<<<dim3(64, 3), 256>>>();
    stats_final_kernel<<<3, 1024>>>(bn_q_g, bn_q_b, bn_k_g, bn_k_b, bn_v_g, bn_v_b);
    fold_kernel<<<dim3(NC, 3), 256>>>(Wq, Wk, Wv);

    // 3 projections (BN folded), split-head rounded output
    gemm_kernel<<<dim3(NT/128, NC/64, 3), 256, GEMM_SMEM>>>(
        cv, cv + (long)NT*NC, cv + (long)2*NT*NC,
        wf, (long)NC*NC, bf, pr, (long)NT*NC, 1, 1);

    // flash attention on tensor cores
    attn_mma_kernel<<<dim3(NB*NH, NL/64), 128, ATTN_SMEM>>>(
        pr, pr + (long)NT*NC, pr + (long)2*NT*NC, ao);

    // output projection (fp32 output, no rounding)
    gemm_kernel<<<dim3(NT/128, NC/64, 1), 256, GEMM_SMEM>>>(
        ao, ao, ao, wo, 0, bo, out, 0, 0, 0);
}

// round 10
// speedup vs baseline: 5.2230x; 1.3941x over previous
#include <cuda_runtime.h>
#include <cuda_fp16.h>
#include <math.h>
#include <cstdint>

#define NB 8
#define NL 1024
#define NC 256
#define NH 8
#define HD 32
#define NT (NB*NL)   /* 8192 tokens */

// ------------------------- scratch (device globals) -------------------------
static __device__ __align__(16) __half g_x16[NT*NC];     // fp16 x, word-permuted ci
static __device__ __align__(16) __half g_y16[NT*NC];     // fp16 y, word-permuted ci
static __device__ __align__(16) __half g_wt16[3*9*NC*NC];// conv w [conv][tap][co][ci-perm]
static __device__ float g_cv[3*NT*NC];     // conv outputs q/k/v
static __device__ float g_pr[3*NT*NC];     // projected q/k/v [B,H,L,d]
static __device__ float g_ao[NT*NC];       // attention output [B,L,C]
static __device__ float g_part[3*64*2*NC];
static __device__ float g_ab[3*2*NC];
static __device__ float g_wf[3*NC*NC];     // BN-folded proj weights (rounded)
static __device__ float g_bf[3*NC];
static __device__ float g_wo[NC*NC];       // rounded Wo

// ------------------------------ helpers -------------------------------------
__device__ __forceinline__ uint32_t to_tf32(float f) {
    uint32_t r;
    asm("cvt.rna.tf32.f32 %0, %1;" : "=r"(r) : "f"(f));
    return r;
}
__device__ __forceinline__ float rndf(float f) {
    return __uint_as_float(to_tf32(f));
}
__device__ __forceinline__ uint32_t cvta_s(const void* p) {
    return (uint32_t)__cvta_generic_to_shared(p);
}
__device__ __forceinline__ void cp16(uint32_t d, const void* s, uint32_t sz) {
    asm volatile("cp.async.cg.shared.global [%0], [%1], 16, %2;"
                 :: "r"(d), "l"(s), "r"(sz));
}
#define CP_COMMIT() asm volatile("cp.async.commit_group;")
#define CP_WAIT1()  asm volatile("cp.async.wait_group 1;")
#define CP_WAIT0()  asm volatile("cp.async.wait_group 0;")

__device__ __forceinline__ void mma_tf32(float* c, const uint32_t* a, const uint32_t* b) {
    asm volatile(
        "mma.sync.aligned.m16n8k8.row.col.f32.tf32.tf32.f32 "
        "{%0,%1,%2,%3}, {%4,%5,%6,%7}, {%8,%9}, {%0,%1,%2,%3};"
        : "+f"(c[0]), "+f"(c[1]), "+f"(c[2]), "+f"(c[3])
        : "r"(a[0]), "r"(a[1]), "r"(a[2]), "r"(a[3]), "r"(b[0]), "r"(b[1]));
}
__device__ __forceinline__ void mma_f16(float* c, const uint32_t* a, const uint32_t* b) {
    asm volatile(
        "mma.sync.aligned.m16n8k16.row.col.f32.f16.f16.f32 "
        "{%0,%1,%2,%3}, {%4,%5,%6,%7}, {%8,%9}, {%0,%1,%2,%3};"
        : "+f"(c[0]), "+f"(c[1]), "+f"(c[2]), "+f"(c[3])
        : "r"(a[0]), "r"(a[1]), "r"(a[2]), "r"(a[3]), "r"(b[0]), "r"(b[1]));
}
#define U(x) __float_as_uint(x)

// word permutation within each 8-word group: storage j holds orig perm8(j)
// perm: 0->0 1->4 2->1 3->5 4->2 5->6 6->3 7->7
__device__ __forceinline__ int perm8(int j) { return ((j & 1) << 2) | (j >> 1); }

// ---------------------------------------------------------------------------
// Implicit 3x3 conv on fp16 tensor cores (m16n8k16), halo smem reuse.
// Tile: M=128 tokens (4 image rows x 32 cols) x N=64 co. 8 warps (4m x 2n),
// warp tile 32x32. K-loop: 16 ci-chunks of 16; per chunk all 9 taps off smem.
// A halo: [6 rows][34 cols][16 ci fp16], B: [9 taps][64 co][16 ci fp16].
// Storage word-permuted so each fragment is LDS.64 (conflict-free 8c+2tq).
// grid (64, 4, 3). Double-buffered cp.async. fp32 accum, output tf32-rounded.
// ---------------------------------------------------------------------------
#define CONV_A_H 3264   /* 204 cells * 16 halves per stage */
#define CONV_B_H 9216   /* 576 rows * 16 halves per stage */
#define CONV_NCH 16     /* 16 chunks x 16 ci = 256 input channels */

__global__ __launch_bounds__(256, 3) void conv_gemm_kernel()
{
    extern __shared__ __half smh[];
    __half* sA[2] = { smh, smh + CONV_A_H };
    __half* sB[2] = { smh + 2*CONV_A_H, smh + 2*CONV_A_H + CONV_B_H };

    const int z = blockIdx.z;
    const __half* Ain = (z == 0) ? g_x16 : g_y16;
    const __half* Wtz = g_wt16 + (long)z * 9*NC*NC;
    float* out = g_cv + (long)z * NT*NC;

    const int tid = threadIdx.x;
    const int wid = tid >> 5, lane = tid & 31;
    const int gID = lane >> 2, tq = lane & 3;
    const int wm = (wid >> 1) * 32, wn = (wid & 1) * 32;
    const int m0 = blockIdx.x * 128, n0 = blockIdx.y * 64;
    const int bImg = blockIdx.x >> 3;
    const int r0b  = (blockIdx.x & 7) * 4;

    auto load_stage = [&](int cc, int st) {
        const int ci0 = cc * 16;
        // A halo: 204 cells x 32B = 408 16B granules
        for (int q = tid; q < 408; q += 256) {
            const int cell = q >> 1, h8 = q & 1;
            const int hr = cell / 34, hc = cell - hr*34;
            const int ir = r0b + hr - 1, ic = hc - 1;
            const bool ok = ((unsigned)ir < 32u) && ((unsigned)ic < 32u);
            const __half* src = ok ? &Ain[((bImg<<10) + ir*32 + ic)*NC + ci0 + h8*8]
                                   : Ain;
            cp16(cvta_s(&sA[st][cell*16 + h8*8]), src, ok ? 16 : 0);
        }
        // B: 576 rows x 32B = 1152 granules
        for (int q = tid; q < 1152; q += 256) {
            const int rowc = q >> 1, h8 = q & 1;
            const int tap = rowc >> 6, co = rowc & 63;
            const __half* src = &Wtz[((tap<<8) + n0 + co)*NC + ci0 + h8*8];
            cp16(cvta_s(&sB[st][rowc*16 + h8*8]), src, 16);
        }
    };

    float acc[2][4][4];
    #pragma unroll
    for (int i = 0; i < 2; i++)
        #pragma unroll
        for (int j = 0; j < 4; j++)
            #pragma unroll
            for (int c = 0; c < 4; c++) acc[i][j][c] = 0.f;

    load_stage(0, 0); CP_COMMIT();

    for (int cc = 0; cc < CONV_NCH; cc++) {
        const int cur = cc & 1;
        if (cc + 1 < CONV_NCH) { load_stage(cc + 1, cur ^ 1); CP_COMMIT(); CP_WAIT1(); }
        else                   { CP_WAIT0(); }
        __syncthreads();
        const __half* a = sA[cur];
        const __half* b = sB[cur];

        #pragma unroll
        for (int tap = 0; tap < 9; tap++) {
            const int d3 = tap / 3, m3 = tap - d3*3;
            uint32_t bf2[4][2];
            #pragma unroll
            for (int nt = 0; nt < 4; nt++) {
                // one LDS.64: (b0 = k[2tq,2tq+1], b1 = k[2tq+8,2tq+9])
                const uint2 bv = *(const uint2*)&b[(tap*64 + wn + nt*8 + gID)*16 + tq*4];
                bf2[nt][0] = bv.x; bf2[nt][1] = bv.y;
            }
            #pragma unroll
            for (int mt = 0; mt < 2; mt++) {
                const int base = wm + mt*16;
                const int rA = base >> 5, cA0 = base & 31;
                const int cell = (rA + d3)*34 + cA0 + gID + m3;
                const uint2 a02 = *(const uint2*)&a[cell*16 + tq*4];       // row gID
                const uint2 a13 = *(const uint2*)&a[(cell + 8)*16 + tq*4]; // row gID+8
                uint32_t af[4] = { a02.x, a13.x, a02.y, a13.y };
                #pragma unroll
                for (int nt = 0; nt < 4; nt++)
                    mma_f16(acc[mt][nt], af, bf2[nt]);
            }
        }
        __syncthreads();
    }

    #pragma unroll
    for (int mt = 0; mt < 2; mt++) {
        #pragma unroll
        for (int half = 0; half < 2; half++) {
            const int t = m0 + wm + mt*16 + gID + half*8;
            #pragma unroll
            for (int nt = 0; nt < 4; nt++) {
                const int n = n0 + wn + nt*8 + tq*2;
                float2 v = { rndf(acc[mt][nt][half*2 + 0]),
                             rndf(acc[mt][nt][half*2 + 1]) };
                *(float2*)&out[t*NC + n] = v;
            }
        }
    }
}

// ---------------------------------------------------------------------------
// Plain tensor-core GEMM (tf32): out[t,n] = sum_k A[t,k]*Bw[n,k] (+bias).
// Tile M=128 x N=64, 8 warps (4m x 2n, warp 32x32), K-chunks of 32.
// ---------------------------------------------------------------------------
__global__ __launch_bounds__(256) void gemm_kernel(
    const float* __restrict__ A0, const float* __restrict__ A1,
    const float* __restrict__ A2,
    const float* __restrict__ B0, long bStride,
    const float* __restrict__ bias0, float* __restrict__ out0, long oStride,
    int split, int rnd)
{
    extern __shared__ float sm[];
    float* sA[2] = { sm, sm + 4608 };
    float* sB[2] = { sm + 9216, sm + 9216 + 2304 };

    const int z = blockIdx.z;
    const float* A    = (z == 0) ? A0 : ((z == 1) ? A1 : A2);
    const float* Bw   = B0 + (long)z * bStride;
    const float* bias = bias0 ? (bias0 + z*NC) : nullptr;
    float* out        = out0 + (long)z * oStride;

    const int tid = threadIdx.x;
    const int wid = tid >> 5, lane = tid & 31;
    const int gID = lane >> 2, tq = lane & 3;
    const int wm = (wid >> 1) * 32, wn = (wid & 1) * 32;
    const int m0 = blockIdx.x * 128, n0 = blockIdx.y * 64;

    auto load_stage = [&](int ch, int st) {
        const int k0 = ch * 32;
        #pragma unroll
        for (int u = 0; u < 4; u++) {
            const int q = u*256 + tid, row = q >> 3, c4 = q & 7;
            cp16(cvta_s(&sA[st][row*36 + c4*4]), &A[(m0+row)*NC + k0 + c4*4], 16);
        }
        #pragma unroll
        for (int u = 0; u < 2; u++) {
            const int q = u*256 + tid, row = q >> 3, c4 = q & 7;
            cp16(cvta_s(&sB[st][row*36 + c4*4]), &Bw[(n0+row)*NC + k0 + c4*4], 16);
        }
    };

    float acc[2][4][4];
    #pragma unroll
    for (int i = 0; i < 2; i++)
        #pragma unroll
        for (int j = 0; j < 4; j++)
            #pragma unroll
            for (int c = 0; c < 4; c++) acc[i][j][c] = 0.f;

    load_stage(0, 0); CP_COMMIT();

    for (int ch = 0; ch < 8; ch++) {
        const int cur = ch & 1;
        if (ch + 1 < 8) { load_stage(ch + 1, cur ^ 1); CP_COMMIT(); CP_WAIT1(); }
        else            { CP_WAIT0(); }
        __syncthreads();

        #pragma unroll
        for (int kk = 0; kk < 32; kk += 8) {
            uint32_t bf2[4][2];
            #pragma unroll
            for (int nt = 0; nt < 4; nt++) {
                const float* pb = &sB[cur][(wn + nt*8 + gID)*36 + kk + tq];
                bf2[nt][0] = U(pb[0]); bf2[nt][1] = U(pb[4]);
            }
            #pragma unroll
            for (int mt = 0; mt < 2; mt++) {
                const float* pa = &sA[cur][(wm + mt*16 + gID)*36 + kk + tq];
                uint32_t af[4] = { U(pa[0]), U(pa[8*36]), U(pa[4]), U(pa[8*36+4]) };
                #pragma unroll
                for (int nt = 0; nt < 4; nt++)
                    mma_tf32(acc[mt][nt], af, bf2[nt]);
            }
        }
        __syncthreads();
    }

    #pragma unroll
    for (int mt = 0; mt < 2; mt++) {
        #pragma unroll
        for (int half = 0; half < 2; half++) {
            const int t = m0 + wm + mt*16 + gID + half*8;
            #pragma unroll
            for (int nt = 0; nt < 4; nt++) {
                const int n = n0 + wn + nt*8 + tq*2;
                float v0 = acc[mt][nt][half*2 + 0];
                float v1 = acc[mt][nt][half*2 + 1];
                if (bias) { v0 += bias[n]; v1 += bias[n+1]; }
                if (rnd)  { v0 = rndf(v0); v1 = rndf(v1); }
                float2 v = { v0, v1 };
                if (split) {
                    const int bb = t >> 10, tt = t & 1023;
                    const int h = n >> 5, d = n & 31;
                    *(float2*)&out[((bb*NH + h)*NL + tt)*HD + d] = v;
                } else {
                    *(float2*)&out[t*NC + n] = v;
                }
            }
        }
    }
}

// ---------------------------------------------------------------------------
// Tensor-core flash attention (tf32 mma, fp32 softmax). Operands pre-rounded.
// Block = 128 threads (4 warps x 16 q rows). grid (64 bh, 16 q-tiles).
// ---------------------------------------------------------------------------
#define KSA 36
#define VS 40
#define PS 68

__global__ __launch_bounds__(128) void attn_mma_kernel(
    const float* __restrict__ Q, const float* __restrict__ K,
    const float* __restrict__ V, float* __restrict__ out)
{
    extern __shared__ float sm[];
    float* sK[2] = { sm, sm + 64*KSA };
    float* sV[2] = { sm + 2*64*KSA, sm + 2*64*KSA + 64*VS };
    float* sP    = sm + 2*64*KSA + 2*64*VS;   // 64 x PS

    const int bh = blockIdx.x, qt = blockIdx.y;
    const int tid = threadIdx.x, w = tid >> 5, lane = tid & 31;
    const int gID = lane >> 2, tq = lane & 3;
    const int r0 = qt*64 + w*16;
    const float* Qb = Q + (long)bh*NL*HD;
    const float* Kb = K + (long)bh*NL*HD;
    const float* Vb = V + (long)bh*NL*HD;

    const float scale = 0.0625f;   // exact power of two: tf32-safe
    uint32_t qf[4][4];
    #pragma unroll
    for (int ks = 0; ks < 4; ks++) {
        qf[ks][0] = U(Qb[(r0+gID  )*HD + ks*8 + tq    ] * scale);
        qf[ks][1] = U(Qb[(r0+gID+8)*HD + ks*8 + tq    ] * scale);
        qf[ks][2] = U(Qb[(r0+gID  )*HD + ks*8 + tq + 4] * scale);
        qf[ks][3] = U(Qb[(r0+gID+8)*HD + ks*8 + tq + 4] * scale);
    }

    float m0 = -1e30f, m1 = -1e30f, l0 = 0.f, l1 = 0.f;
    float oacc[4][4];
    #pragma unroll
    for (int i = 0; i < 4; i++)
        #pragma unroll
        for (int j = 0; j < 4; j++) oacc[i][j] = 0.f;

    auto load_kv = [&](int kt, int st) {
        #pragma unroll
        for (int u = 0; u < 4; u++) {
            const int idx = u*128 + tid, row = idx >> 3, c4 = idx & 7;
            cp16(cvta_s(&sK[st][row*KSA + c4*4]), &Kb[(kt*64 + row)*HD + c4*4], 16);
            cp16(cvta_s(&sV[st][row*VS  + c4*4]), &Vb[(kt*64 + row)*HD + c4*4], 16);
        }
    };

    load_kv(0, 0); CP_COMMIT();

    for (int kt = 0; kt < 16; kt++) {
        const int cur = kt & 1;
        if (kt + 1 < 16) { load_kv(kt + 1, cur ^ 1); CP_COMMIT(); CP_WAIT1(); }
        else             { CP_WAIT0(); }
        __syncthreads();

        // S = Q K^T (16 x 64 per warp)
        float sacc[8][4];
        #pragma unroll
        for (int nt = 0; nt < 8; nt++)
            #pragma unroll
            for (int c = 0; c < 4; c++) sacc[nt][c] = 0.f;
        #pragma unroll
        for (int kk = 0; kk < 4; kk++) {
            #pragma unroll
            for (int nt = 0; nt < 8; nt++) {
                const float* pb = &sK[cur][(nt*8 + gID)*KSA + kk*8 + tq];
                uint32_t b[2] = { U(pb[0]), U(pb[4]) };
                mma_tf32(sacc[nt], qf[kk], b);
            }
        }

        // online softmax
        float mx0 = -1e30f, mx1 = -1e30f;
        #pragma unroll
        for (int nt = 0; nt < 8; nt++) {
            mx0 = fmaxf(mx0, fmaxf(sacc[nt][0], sacc[nt][1]));
            mx1 = fmaxf(mx1, fmaxf(sacc[nt][2], sacc[nt][3]));
        }
        mx0 = fmaxf(mx0, __shfl_xor_sync(~0u, mx0, 1));
        mx0 = fmaxf(mx0, __shfl_xor_sync(~0u, mx0, 2));
        mx1 = fmaxf(mx1, __shfl_xor_sync(~0u, mx1, 1));
        mx1 = fmaxf(mx1, __shfl_xor_sync(~0u, mx1, 2));
        const float mn0 = fmaxf(m0, mx0), mn1 = fmaxf(m1, mx1);
        const float c0 = __expf(m0 - mn0), c1 = __expf(m1 - mn1);

        float s0 = 0.f, s1 = 0.f;
        #pragma unroll
        for (int nt = 0; nt < 8; nt++) {
            float p0 = __expf(sacc[nt][0] - mn0);
            float p1 = __expf(sacc[nt][1] - mn0);
            float p2 = __expf(sacc[nt][2] - mn1);
            float p3 = __expf(sacc[nt][3] - mn1);
            s0 += p0 + p1; s1 += p2 + p3;
            float* pr  = &sP[(w*16 + gID    )*PS + nt*8 + tq*2];
            float* pr2 = &sP[(w*16 + gID + 8)*PS + nt*8 + tq*2];
            pr[0]  = rndf(p0); pr[1]  = rndf(p1);
            pr2[0] = rndf(p2); pr2[1] = rndf(p3);
        }
        s0 += __shfl_xor_sync(~0u, s0, 1); s0 += __shfl_xor_sync(~0u, s0, 2);
        s1 += __shfl_xor_sync(~0u, s1, 1); s1 += __shfl_xor_sync(~0u, s1, 2);
        l0 = l0*c0 + s0; l1 = l1*c1 + s1;
        #pragma unroll
        for (int nt = 0; nt < 4; nt++) {
            oacc[nt][0] *= c0; oacc[nt][1] *= c0;
            oacc[nt][2] *= c1; oacc[nt][3] *= c1;
        }
        m0 = mn0; m1 = mn1;
        __syncwarp();

        // O += P V
        #pragma unroll
        for (int kk = 0; kk < 8; kk++) {
            const float* pb = &sP[(w*16 + gID)*PS + kk*8 + tq];
            uint32_t pa[4] = { U(pb[0]), U(pb[8*PS]), U(pb[4]), U(pb[8*PS + 4]) };
            #pragma unroll
            for (int nt = 0; nt < 4; nt++) {
                uint32_t vb[2] = { U(sV[cur][(kk*8 + tq    )*VS + nt*8 + gID]),
                                   U(sV[cur][(kk*8 + tq + 4)*VS + nt*8 + gID]) };
                mma_tf32(oacc[nt], pa, vb);
            }
        }
        __syncthreads();
    }

    const float i0 = 1.f / l0, i1 = 1.f / l1;
    const int b = bh >> 3, h = bh & 7;
    #pragma unroll
    for (int nt = 0; nt < 4; nt++) {
        const int col = h*HD + nt*8 + tq*2;
        float2 v0 = { rndf(oacc[nt][0]*i0), rndf(oacc[nt][1]*i0) };
        float2 v1 = { rndf(oacc[nt][2]*i1), rndf(oacc[nt][3]*i1) };
        *(float2*)&out[(b*NL + r0 + gID    )*NC + col] = v0;
        *(float2*)&out[(b*NL + r0 + gID + 8)*NC + col] = v1;
    }
}

// ------------------------ small prep / stats kernels ------------------------
// x/y -> fp16 with word-permuted channel layout (16-ch groups, 8 half2 words)
__global__ __launch_bounds__(256) void cvt_xy_kernel(
    const float* __restrict__ x, const float* __restrict__ y)
{
    const float* s = blockIdx.y ? y : x;
    __half* d = blockIdx.y ? g_y16 : g_x16;
    const int i8 = blockIdx.x * 256 + threadIdx.x;   // 8-half granule id
    const int base = i8 * 8;
    const int token = base >> 8;
    const int cs0 = base & 255;
    __half tmp[8];
    #pragma unroll
    for (int jj = 0; jj < 8; jj++) {
        const int cs = cs0 + jj;
        const int group = cs >> 4, j = cs & 15, wd = j >> 1, h = j & 1;
        const int orig = (group << 4) + (perm8(wd) << 1) + h;
        tmp[jj] = __float2half_rn(s[token*NC + orig]);
    }
    *(uint4*)&d[base] = *(const uint4*)tmp;
}

__global__ __launch_bounds__(256) void round_wo_kernel(const float* __restrict__ Wo)
{
    const int i = (blockIdx.x * 256 + threadIdx.x) * 4;
    float4 v = *(const float4*)(Wo + i);
    v.x = rndf(v.x); v.y = rndf(v.y); v.z = rndf(v.z); v.w = rndf(v.w);
    *(float4*)(g_wo + i) = v;
}

// conv weights -> fp16 [conv][tap][co][ci], ci word-permuted to match g_x16
__global__ __launch_bounds__(256) void wtrans_kernel(
    const float* __restrict__ wq, const float* __restrict__ wk,
    const float* __restrict__ wv)
{
    const float* W = (blockIdx.y == 0) ? wq : (blockIdx.y == 1) ? wk : wv;
    __half* dst = g_wt16 + (long)blockIdx.y * 9*NC*NC;
    const int idx = blockIdx.x * 256 + threadIdx.x;
    const int ci  = idx & 255;
    const int rem = idx >> 8;
    const int co  = rem & 255;
    const int tap = rem >> 8;
    const int group = ci >> 4, j = ci & 15, wd = j >> 1, h = j & 1;
    const int orig_ci = (group << 4) + (perm8(wd) << 1) + h;
    dst[idx] = __float2half_rn(W[(co*NC + orig_ci)*9 + tap]);
}

__global__ __launch_bounds__(256) void stats_partial_kernel()
{
    const float* src = g_cv + (long)blockIdx.y * NT*NC;
    const int c = threadIdx.x;
    float s = 0.f, s2 = 0.f;
    const int t0 = blockIdx.x * (NT/64);
    #pragma unroll 4
    for (int t = t0; t < t0 + NT/64; t++) {
        float val = src[t*NC + c];
        s += val; s2 += val*val;
    }
    g_part[((blockIdx.y*64 + blockIdx.x)*2 + 0)*NC + c] = s;
    g_part[((blockIdx.y*64 + blockIdx.x)*2 + 1)*NC + c] = s2;
}

__global__ __launch_bounds__(1024) void stats_final_kernel(
    const float* __restrict__ gq, const float* __restrict__ bq,
    const float* __restrict__ gk, const float* __restrict__ bk,
    const float* __restrict__ gv, const float* __restrict__ bv)
{
    const int s = blockIdx.x;
    const int c = threadIdx.x & 255;
    const int seg = threadIdx.x >> 8;
    float sum = 0.f, sum2 = 0.f;
    #pragma unroll
    for (int i = seg*16; i < seg*16 + 16; i++) {
        sum  += g_part[((s*64+i)*2 + 0)*NC + c];
        sum2 += g_part[((s*64+i)*2 + 1)*NC + c];
    }
    __shared__ float red[8][256];
    red[seg][c] = sum; red[4+seg][c] = sum2;
    __syncthreads();
    if (seg == 0) {
        sum  = red[0][c] + red[1][c] + red[2][c] + red[3][c];
        sum2 = red[4][c] + red[5][c] + red[6][c] + red[7][c];
        float mu  = sum  * (1.f/NT);
        float var = sum2 * (1.f/NT) - mu*mu;
        const float* gam = (s == 0) ? gq : (s == 1) ? gk : gv;
        const float* bet = (s == 0) ? bq : (s == 1) ? bk : bv;
        float a  = gam[c] * rsqrtf(var + 1e-5f);
        float bb = bet[c] - mu*a;
        g_ab[(s*2+0)*NC + c] = a;
        g_ab[(s*2+1)*NC + c] = bb;
    }
}

__global__ __launch_bounds__(256) void fold_kernel(
    const float* __restrict__ Wq, const float* __restrict__ Wk,
    const float* __restrict__ Wv)
{
    const int s  = blockIdx.y;
    const int co = blockIdx.x;
    const int c  = threadIdx.x;
    const float* W = (s == 0) ? Wq : (s == 1) ? Wk : Wv;
    float a  = g_ab[(s*2+0)*NC + c];
    float bb = g_ab[(s*2+1)*NC + c];
    float wv = W[co*NC + c];
    g_wf[s*NC*NC + co*NC + c] = rndf(wv * a);

    __shared__ float red[256];
    red[c] = wv * bb;
    __syncthreads();
    for (int o = 128; o > 0; o >>= 1) {
        if (c < o) red[c] += red[c + o];
        __syncthreads();
    }
    if (c == 0) g_bf[s*NC + co] = red[0];
}

// ---------------------------------------------------------------------------

extern "C" void kernel_launch(void* const* d_in, const int* in_sizes, int n_in,
                              void* d_out, int out_size)
{
    const float* x        = (const float*)d_in[0];
    const float* y        = (const float*)d_in[1];
    const float* conv_q_w = (const float*)d_in[4];
    const float* bn_q_g   = (const float*)d_in[5];
    const float* bn_q_b   = (const float*)d_in[6];
    const float* conv_k_w = (const float*)d_in[7];
    const float* bn_k_g   = (const float*)d_in[8];
    const float* bn_k_b   = (const float*)d_in[9];
    const float* conv_v_w = (const float*)d_in[10];
    const float* bn_v_g   = (const float*)d_in[11];
    const float* bn_v_b   = (const float*)d_in[12];
    const float* Wq       = (const float*)d_in[13];
    const float* Wk       = (const float*)d_in[14];
    const float* Wv       = (const float*)d_in[15];
    const float* Wo       = (const float*)d_in[16];
    const float* bo       = (const float*)d_in[17];
    float* out = (float*)d_out;

    float *cv, *pr, *ao, *wf, *bf, *wo;
    cudaGetSymbolAddress((void**)&cv, g_cv);
    cudaGetSymbolAddress((void**)&pr, g_pr);
    cudaGetSymbolAddress((void**)&ao, g_ao);
    cudaGetSymbolAddress((void**)&wf, g_wf);
    cudaGetSymbolAddress((void**)&bf, g_bf);
    cudaGetSymbolAddress((void**)&wo, g_wo);

    const int CONV_SMEM = (CONV_A_H + CONV_B_H) * 2 * 2;          // 49920 B
    const int GEMM_SMEM = (2*4608 + 2*2304) * 4;                  // 55296 B
    const int ATTN_SMEM = (2*64*KSA + 2*64*VS + 64*PS) * 4;       // 56320 B
    cudaFuncSetAttribute(conv_gemm_kernel,
                         cudaFuncAttributeMaxDynamicSharedMemorySize, CONV_SMEM);
    cudaFuncSetAttribute(gemm_kernel,
                         cudaFuncAttributeMaxDynamicSharedMemorySize, GEMM_SMEM);
    cudaFuncSetAttribute(attn_mma_kernel,
                         cudaFuncAttributeMaxDynamicSharedMemorySize, ATTN_SMEM);

    // operand conversion + permuted weight layout
    cvt_xy_kernel<<<dim3(NT*NC/2048, 2), 256>>>(x, y);
    wtrans_kernel<<<dim3(9*NC, 3), 256>>>(conv_q_w, conv_k_w, conv_v_w);
    round_wo_kernel<<<NC*NC/1024, 256>>>(Wo);

    // 3 convs, halo implicit GEMM on fp16 tensor cores
    conv_gemm_kernel<<<dim3(NT/128, NC/64, 3), 256, CONV_SMEM>>>();

    // BN stats -> fold into projection weights
    stats_partial_kernel<<<dim3(64, 3), 256>>>();
    stats_final_kernel<<<3, 1024>>>(bn_q_g, bn_q_b, bn_k_g, bn_k_b, bn_v_g, bn_v_b);
    fold_kernel<<<dim3(NC, 3), 256>>>(Wq, Wk, Wv);

    // 3 projections (BN folded), split-head rounded output
    gemm_kernel<<<dim3(NT/128, NC/64, 3), 256, GEMM_SMEM>>>(
        cv, cv + (long)NT*NC, cv + (long)2*NT*NC,
        wf, (long)NC*NC, bf, pr, (long)NT*NC, 1, 1);

    // flash attention on tensor cores
    attn_mma_kernel<<<dim3(NB*NH, NL/64), 128, ATTN_SMEM>>>(
        pr, pr + (long)NT*NC, pr + (long)2*NT*NC, ao);

    // output projection (fp32 output, no rounding)
    gemm_kernel<<<dim3(NT/128, NC/64, 1), 256, GEMM_SMEM>>>(
        ao, ao, ao, wo, 0, bo, out, 0, 0, 0);
}

// round 12
// speedup vs baseline: 6.7576x; 1.2938x over previous
#include <cuda_runtime.h>
#include <cuda_fp16.h>
#include <math.h>
#include <cstdint>

#define NB 8
#define NL 1024
#define NC 256
#define NH 8
#define HD 32
#define NT (NB*NL)   /* 8192 tokens */

// ------------------------- scratch (device globals) -------------------------
static __device__ __align__(16) __half g_x16[NT*NC];      // fp16 x, word-permuted ci
static __device__ __align__(16) __half g_y16[NT*NC];      // fp16 y, word-permuted ci
static __device__ __align__(16) __half g_wt16[3*9*NC*NC]; // conv w [conv][tap][co][ci-perm]
static __device__ __align__(16) __half g_cv16[3*NT*NC];   // conv out, word-permuted ch
static __device__ __align__(16) __half g_q16[NT*NC];      // Q [bh][L][32] dim-perm
static __device__ __align__(16) __half g_k16[NT*NC];      // K [bh][L][32] dim-perm
static __device__ __align__(16) __half g_v16t[NT*NC];     // V^T [bh][32][L] tok-perm
static __device__ __align__(16) __half g_ao16[NT*NC];     // attn out [t][256] ch-perm
static __device__ __align__(16) __half g_wf16[3*NC*NC];   // folded proj w, ci-perm
static __device__ __align__(16) __half g_wo16[NC*NC];     // Wo fp16, ci-perm
static __device__ float g_part[3*64*2*NC];
static __device__ float g_ab[3*2*NC];
static __device__ float g_bf[3*NC];

// ------------------------------ helpers -------------------------------------
__device__ __forceinline__ uint32_t cvta_s(const void* p) {
    return (uint32_t)__cvta_generic_to_shared(p);
}
__device__ __forceinline__ void cp16(uint32_t d, const void* s, uint32_t sz) {
    asm volatile("cp.async.cg.shared.global [%0], [%1], 16, %2;"
                 :: "r"(d), "l"(s), "r"(sz));
}
#define CP_COMMIT() asm volatile("cp.async.commit_group;")
#define CP_WAIT1()  asm volatile("cp.async.wait_group 1;")
#define CP_WAIT0()  asm volatile("cp.async.wait_group 0;")

__device__ __forceinline__ void mma_f16(float* c, const uint32_t* a, const uint32_t* b) {
    asm volatile(
        "mma.sync.aligned.m16n8k16.row.col.f32.f16.f16.f32 "
        "{%0,%1,%2,%3}, {%4,%5,%6,%7}, {%8,%9}, {%0,%1,%2,%3};"
        : "+f"(c[0]), "+f"(c[1]), "+f"(c[2]), "+f"(c[3])
        : "r"(a[0]), "r"(a[1]), "r"(a[2]), "r"(a[3]), "r"(b[0]), "r"(b[1]));
}

// word permutation within each 8-word (16-channel) group:
// storage word j holds orig word perm8(j); inv8 is its inverse.
__device__ __forceinline__ int perm8(int j) { return ((j & 1) << 2) | (j >> 1); }
__device__ __forceinline__ int inv8(int w)  { return ((w & 3) << 1) | (w >> 2); }
// storage channel index s -> original channel index
__device__ __forceinline__ int orig_ch(int s) {
    return (s & ~15) | (perm8((s & 15) >> 1) << 1) | (s & 1);
}
__device__ __forceinline__ __half2 f2h2(float a, float b) {
    return __floats2half2_rn(a, b);
}

// ---------------------------------------------------------------------------
// Implicit 3x3 conv on fp16 tensor cores (m16n8k16), halo smem reuse.
// Tile M=128 tokens x N=64 co; 8 warps (4m x 2n), warp 32x32.
// K-loop: 16 ci-chunks of 16. Output: fp16, channel-word-permuted.
// ---------------------------------------------------------------------------
#define CONV_A_H 3264   /* 204 cells * 16 halves */
#define CONV_B_H 9216   /* 576 rows * 16 halves */
#define CONV_NCH 16

__global__ __launch_bounds__(256, 3) void conv_gemm_kernel()
{
    extern __shared__ __half smh[];
    __half* sA[2] = { smh, smh + CONV_A_H };
    __half* sB[2] = { smh + 2*CONV_A_H, smh + 2*CONV_A_H + CONV_B_H };

    const int z = blockIdx.z;
    const __half* Ain = (z == 0) ? g_x16 : g_y16;
    const __half* Wtz = g_wt16 + (long)z * 9*NC*NC;
    __half* outh = g_cv16 + (long)z * NT*NC;

    const int tid = threadIdx.x;
    const int wid = tid >> 5, lane = tid & 31;
    const int gID = lane >> 2, tq = lane & 3;
    const int wm = (wid >> 1) * 32, wn = (wid & 1) * 32;
    const int m0 = blockIdx.x * 128, n0 = blockIdx.y * 64;
    const int bImg = blockIdx.x >> 3;
    const int r0b  = (blockIdx.x & 7) * 4;

    auto load_stage = [&](int cc, int st) {
        const int ci0 = cc * 16;
        for (int q = tid; q < 408; q += 256) {
            const int cell = q >> 1, h8 = q & 1;
            const int hr = cell / 34, hc = cell - hr*34;
            const int ir = r0b + hr - 1, ic = hc - 1;
            const bool ok = ((unsigned)ir < 32u) && ((unsigned)ic < 32u);
            const __half* src = ok ? &Ain[((bImg<<10) + ir*32 + ic)*NC + ci0 + h8*8]
                                   : Ain;
            cp16(cvta_s(&sA[st][cell*16 + h8*8]), src, ok ? 16 : 0);
        }
        for (int q = tid; q < 1152; q += 256) {
            const int rowc = q >> 1, h8 = q & 1;
            const int tap = rowc >> 6, co = rowc & 63;
            const __half* src = &Wtz[((tap<<8) + n0 + co)*NC + ci0 + h8*8];
            cp16(cvta_s(&sB[st][rowc*16 + h8*8]), src, 16);
        }
    };

    float acc[2][4][4];
    #pragma unroll
    for (int i = 0; i < 2; i++)
        #pragma unroll
        for (int j = 0; j < 4; j++)
            #pragma unroll
            for (int c = 0; c < 4; c++) acc[i][j][c] = 0.f;

    load_stage(0, 0); CP_COMMIT();

    for (int cc = 0; cc < CONV_NCH; cc++) {
        const int cur = cc & 1;
        if (cc + 1 < CONV_NCH) { load_stage(cc + 1, cur ^ 1); CP_COMMIT(); CP_WAIT1(); }
        else                   { CP_WAIT0(); }
        __syncthreads();
        const __half* a = sA[cur];
        const __half* b = sB[cur];

        #pragma unroll
        for (int tap = 0; tap < 9; tap++) {
            const int d3 = tap / 3, m3 = tap - d3*3;
            uint32_t bf2[4][2];
            #pragma unroll
            for (int nt = 0; nt < 4; nt++) {
                const uint2 bv = *(const uint2*)&b[(tap*64 + wn + nt*8 + gID)*16 + tq*4];
                bf2[nt][0] = bv.x; bf2[nt][1] = bv.y;
            }
            #pragma unroll
            for (int mt = 0; mt < 2; mt++) {
                const int base = wm + mt*16;
                const int rA = base >> 5, cA0 = base & 31;
                const int cell = (rA + d3)*34 + cA0 + gID + m3;
                const uint2 a02 = *(const uint2*)&a[cell*16 + tq*4];
                const uint2 a13 = *(const uint2*)&a[(cell + 8)*16 + tq*4];
                uint32_t af[4] = { a02.x, a13.x, a02.y, a13.y };
                #pragma unroll
                for (int nt = 0; nt < 4; nt++)
                    mma_f16(acc[mt][nt], af, bf2[nt]);
            }
        }
        __syncthreads();
    }

    #pragma unroll
    for (int mt = 0; mt < 2; mt++) {
        #pragma unroll
        for (int half = 0; half < 2; half++) {
            const int t = m0 + wm + mt*16 + gID + half*8;
            #pragma unroll
            for (int nt = 0; nt < 4; nt++) {
                const int n = n0 + wn + nt*8 + tq*2;
                const int g = n >> 4, wd = (n & 15) >> 1;
                const int off = t*NC + (g << 4) + (inv8(wd) << 1);
                *(__half2*)&outh[off] = f2h2(acc[mt][nt][half*2 + 0],
                                             acc[mt][nt][half*2 + 1]);
            }
        }
    }
}

// ---------------------------------------------------------------------------
// Unified fp16 tensor-core GEMM: out[t,n] = sum_k A[t,k]*B[n,k] (+bias).
// A, B fp16 with word-permuted k. Tile M=128 x N=64, 8 warps, K-chunks of 32.
// Rows padded to 48 halves (bank-conflict-free LDS.64 fragments).
// split=0: fp32 natural out. split=1: per-z fp16 Q/K (dim-perm) or V^T (tok-perm).
// ---------------------------------------------------------------------------
__global__ __launch_bounds__(256) void gemm16_kernel(
    const __half* __restrict__ A0, const __half* __restrict__ A1,
    const __half* __restrict__ A2,
    const __half* __restrict__ B0, long bStride,
    const float* __restrict__ bias0, float* __restrict__ outF, int split)
{
    extern __shared__ __half smh[];
    __half* sA[2] = { smh, smh + 6144 };
    __half* sB[2] = { smh + 12288, smh + 12288 + 3072 };

    const int z = blockIdx.z;
    const __half* A  = (z == 0) ? A0 : ((z == 1) ? A1 : A2);
    const __half* Bw = B0 + (long)z * bStride;
    const float* bias = bias0 ? (bias0 + z*NC) : nullptr;

    const int tid = threadIdx.x;
    const int wid = tid >> 5, lane = tid & 31;
    const int gID = lane >> 2, tq = lane & 3;
    const int wm = (wid >> 1) * 32, wn = (wid & 1) * 32;
    const int m0 = blockIdx.x * 128, n0 = blockIdx.y * 64;

    auto load_stage = [&](int ch, int st) {
        const int k0 = ch * 32;
        #pragma unroll
        for (int u = 0; u < 2; u++) {
            const int q = u*256 + tid, row = q >> 2, gr = q & 3;
            cp16(cvta_s(&sA[st][row*48 + gr*8]), &A[(m0+row)*NC + k0 + gr*8], 16);
        }
        {
            const int row = tid >> 2, gr = tid & 3;
            cp16(cvta_s(&sB[st][row*48 + gr*8]), &Bw[(n0+row)*NC + k0 + gr*8], 16);
        }
    };

    float acc[2][4][4];
    #pragma unroll
    for (int i = 0; i < 2; i++)
        #pragma unroll
        for (int j = 0; j < 4; j++)
            #pragma unroll
            for (int c = 0; c < 4; c++) acc[i][j][c] = 0.f;

    load_stage(0, 0); CP_COMMIT();

    for (int ch = 0; ch < 8; ch++) {
        const int cur = ch & 1;
        if (ch + 1 < 8) { load_stage(ch + 1, cur ^ 1); CP_COMMIT(); CP_WAIT1(); }
        else            { CP_WAIT0(); }
        __syncthreads();
        const __half* a = sA[cur];
        const __half* b = sB[cur];

        #pragma unroll
        for (int g2 = 0; g2 < 2; g2++) {
            uint32_t bf2[4][2];
            #pragma unroll
            for (int nt = 0; nt < 4; nt++) {
                const uint2 bv = *(const uint2*)&b[(wn + nt*8 + gID)*48 + g2*16 + tq*4];
                bf2[nt][0] = bv.x; bf2[nt][1] = bv.y;
            }
            #pragma unroll
            for (int mt = 0; mt < 2; mt++) {
                const __half* pa = &a[(wm + mt*16 + gID)*48 + g2*16 + tq*4];
                const uint2 a02 = *(const uint2*)pa;
                const uint2 a13 = *(const uint2*)&pa[8*48];
                uint32_t af[4] = { a02.x, a13.x, a02.y, a13.y };
                #pragma unroll
                for (int nt = 0; nt < 4; nt++)
                    mma_f16(acc[mt][nt], af, bf2[nt]);
            }
        }
        __syncthreads();
    }

    #pragma unroll
    for (int mt = 0; mt < 2; mt++) {
        #pragma unroll
        for (int half = 0; half < 2; half++) {
            const int t = m0 + wm + mt*16 + gID + half*8;
            #pragma unroll
            for (int nt = 0; nt < 4; nt++) {
                const int n = n0 + wn + nt*8 + tq*2;
                float v0 = acc[mt][nt][half*2 + 0];
                float v1 = acc[mt][nt][half*2 + 1];
                if (bias) { v0 += bias[n]; v1 += bias[n+1]; }
                if (!split) {
                    float2 v = { v0, v1 };
                    *(float2*)&outF[t*NC + n] = v;
                } else {
                    const int bb = t >> 10, tt = t & 1023;
                    const int h = n >> 5, d = n & 31;
                    if (z < 2) {
                        __half* dst = (z == 0) ? g_q16 : g_k16;
                        const int g = d >> 4, wd = (d & 15) >> 1;
                        const int off = ((bb*NH + h)*NL + tt)*HD + (g << 4) + (inv8(wd) << 1);
                        *(__half2*)&dst[off] = f2h2(v0, v1);
                    } else {
                        const int wt = (tt & 15) >> 1;
                        const int tp = (tt & ~15) | (inv8(wt) << 1) | (tt & 1);
                        const long base = (long)(bb*NH + h) * HD;
                        g_v16t[(base + d    )*NL + tp] = __float2half_rn(v0);
                        g_v16t[(base + d + 1)*NL + tp] = __float2half_rn(v1);
                    }
                }
            }
        }
    }
}

// ---------------------------------------------------------------------------
// fp16 tensor-core flash attention; fp32 softmax.
// Block = 128 threads (4 warps x 16 q rows). grid (64 bh, 16 q-tiles).
// K: [64 tok][32 dim-perm] stride 48; V^T: [32 dim][64 tok-perm] stride 80;
// P: [64 q][64 tok-perm half] stride 80. All fragments LDS.64, conflict-free.
// ---------------------------------------------------------------------------
#define ARS 48
#define AVS 80
#define APS 80

__global__ __launch_bounds__(128) void attn16_kernel()
{
    extern __shared__ __half smh[];
    __half* sK[2]  = { smh, smh + 64*ARS };
    __half* sVt[2] = { smh + 2*64*ARS, smh + 2*64*ARS + 32*AVS };
    __half* sP     = smh + 2*64*ARS + 2*32*AVS;

    const int bh = blockIdx.x, qt = blockIdx.y;
    const int tid = threadIdx.x, w = tid >> 5, lane = tid & 31;
    const int gID = lane >> 2, tq = lane & 3;
    const int r0 = qt*64 + w*16;
    const __half* Qb = g_q16 + (long)bh*NL*HD;
    const __half* Kb = g_k16 + (long)bh*NL*HD;
    const __half* Vb = g_v16t + (long)bh*HD*NL;   // [32][1024]

    const __half2 sc2 = __floats2half2_rn(0.0625f, 0.0625f);
    uint32_t qf[2][4];
    #pragma unroll
    for (int g = 0; g < 2; g++) {
        uint2 lo = *(const uint2*)&Qb[(r0+gID  )*HD + g*16 + tq*4];
        uint2 hi = *(const uint2*)&Qb[(r0+gID+8)*HD + g*16 + tq*4];
        __half2 t;
        t = __hmul2(*(__half2*)&lo.x, sc2); qf[g][0] = *(uint32_t*)&t;
        t = __hmul2(*(__half2*)&hi.x, sc2); qf[g][1] = *(uint32_t*)&t;
        t = __hmul2(*(__half2*)&lo.y, sc2); qf[g][2] = *(uint32_t*)&t;
        t = __hmul2(*(__half2*)&hi.y, sc2); qf[g][3] = *(uint32_t*)&t;
    }

    float m0 = -1e30f, m1 = -1e30f, l0 = 0.f, l1 = 0.f;
    float oacc[4][4];
    #pragma unroll
    for (int i = 0; i < 4; i++)
        #pragma unroll
        for (int j = 0; j < 4; j++) oacc[i][j] = 0.f;

    auto load_kv = [&](int kt, int st) {
        #pragma unroll
        for (int u = 0; u < 2; u++) {
            const int q = u*128 + tid, row = q >> 2, gr = q & 3;
            cp16(cvta_s(&sK[st][row*ARS + gr*8]), &Kb[(kt*64 + row)*HD + gr*8], 16);
        }
        #pragma unroll
        for (int u = 0; u < 2; u++) {
            const int q = u*128 + tid, row = q >> 3, gr = q & 7;
            cp16(cvta_s(&sVt[st][row*AVS + gr*8]), &Vb[row*NL + kt*64 + gr*8], 16);
        }
    };

    load_kv(0, 0); CP_COMMIT();

    for (int kt = 0; kt < 16; kt++) {
        const int cur = kt & 1;
        if (kt + 1 < 16) { load_kv(kt + 1, cur ^ 1); CP_COMMIT(); CP_WAIT1(); }
        else             { CP_WAIT0(); }
        __syncthreads();

        // S = Q K^T (16 x 64 per warp): 16 MMAs
        float sacc[8][4];
        #pragma unroll
        for (int nt = 0; nt < 8; nt++)
            #pragma unroll
            for (int c = 0; c < 4; c++) sacc[nt][c] = 0.f;
        #pragma unroll
        for (int g = 0; g < 2; g++) {
            #pragma unroll
            for (int nt = 0; nt < 8; nt++) {
                const uint2 bv = *(const uint2*)&sK[cur][(nt*8 + gID)*ARS + g*16 + tq*4];
                uint32_t bf[2] = { bv.x, bv.y };
                mma_f16(sacc[nt], qf[g], bf);
            }
        }

        // online softmax
        float mx0 = -1e30f, mx1 = -1e30f;
        #pragma unroll
        for (int nt = 0; nt < 8; nt++) {
            mx0 = fmaxf(mx0, fmaxf(sacc[nt][0], sacc[nt][1]));
            mx1 = fmaxf(mx1, fmaxf(sacc[nt][2], sacc[nt][3]));
        }
        mx0 = fmaxf(mx0, __shfl_xor_sync(~0u, mx0, 1));
        mx0 = fmaxf(mx0, __shfl_xor_sync(~0u, mx0, 2));
        mx1 = fmaxf(mx1, __shfl_xor_sync(~0u, mx1, 1));
        mx1 = fmaxf(mx1, __shfl_xor_sync(~0u, mx1, 2));
        const float mn0 = fmaxf(m0, mx0), mn1 = fmaxf(m1, mx1);
        const float c0 = __expf(m0 - mn0), c1 = __expf(m1 - mn1);

        float s0 = 0.f, s1 = 0.f;
        #pragma unroll
        for (int nt = 0; nt < 8; nt++) {
            float p0 = __expf(sacc[nt][0] - mn0);
            float p1 = __expf(sacc[nt][1] - mn0);
            float p2 = __expf(sacc[nt][2] - mn1);
            float p3 = __expf(sacc[nt][3] - mn1);
            s0 += p0 + p1; s1 += p2 + p3;
            const int colw = nt*8 + tq*2;
            const int po = ((colw >> 4) << 4) + inv8((colw & 15) >> 1)*2;
            *(__half2*)&sP[(w*16 + gID    )*APS + po] = f2h2(p0, p1);
            *(__half2*)&sP[(w*16 + gID + 8)*APS + po] = f2h2(p2, p3);
        }
        s0 += __shfl_xor_sync(~0u, s0, 1); s0 += __shfl_xor_sync(~0u, s0, 2);
        s1 += __shfl_xor_sync(~0u, s1, 1); s1 += __shfl_xor_sync(~0u, s1, 2);
        l0 = l0*c0 + s0; l1 = l1*c1 + s1;
        #pragma unroll
        for (int nt = 0; nt < 4; nt++) {
            oacc[nt][0] *= c0; oacc[nt][1] *= c0;
            oacc[nt][2] *= c1; oacc[nt][3] *= c1;
        }
        m0 = mn0; m1 = mn1;
        __syncwarp();

        // O += P V : 16 MMAs
        #pragma unroll
        for (int ks = 0; ks < 4; ks++) {
            const __half* prow = &sP[(w*16 + gID)*APS + ks*16 + tq*4];
            const uint2 a02 = *(const uint2*)prow;
            const uint2 a13 = *(const uint2*)&prow[8*APS];
            uint32_t pa[4] = { a02.x, a13.x, a02.y, a13.y };
            #pragma unroll
            for (int nt = 0; nt < 4; nt++) {
                const uint2 bv = *(const uint2*)&sVt[cur][(nt*8 + gID)*AVS + ks*16 + tq*4];
                uint32_t vb[2] = { bv.x, bv.y };
                mma_f16(oacc[nt], pa, vb);
            }
        }
        __syncthreads();
    }

    const float i0 = 1.f / l0, i1 = 1.f / l1;
    const int b = bh >> 3, h = bh & 7;
    #pragma unroll
    for (int nt = 0; nt < 4; nt++) {
        const int ch = h*HD + nt*8 + tq*2;
        const int off = ((ch >> 4) << 4) + inv8((ch & 15) >> 1)*2;
        *(__half2*)&g_ao16[(b*NL + r0 + gID    )*NC + off] =
            f2h2(oacc[nt][0]*i0, oacc[nt][1]*i0);
        *(__half2*)&g_ao16[(b*NL + r0 + gID + 8)*NC + off] =
            f2h2(oacc[nt][2]*i1, oacc[nt][3]*i1);
    }
}

// ------------------------ small prep / stats kernels ------------------------
__global__ __launch_bounds__(256) void cvt_xy_kernel(
    const float* __restrict__ x, const float* __restrict__ y)
{
    const float* s = blockIdx.y ? y : x;
    __half* d = blockIdx.y ? g_y16 : g_x16;
    const int base = (blockIdx.x * 256 + threadIdx.x) * 8;
    const int token = base >> 8;
    const int cs0 = base & 255;
    __half tmp[8];
    #pragma unroll
    for (int jj = 0; jj < 8; jj++)
        tmp[jj] = __float2half_rn(s[token*NC + orig_ch(cs0 + jj)]);
    *(uint4*)&d[base] = *(const uint4*)tmp;
}

__global__ __launch_bounds__(256) void round_wo_kernel(const float* __restrict__ Wo)
{
    const int idx = blockIdx.x * 256 + threadIdx.x;   // co*256 + storage ci
    const int ci = idx & 255, co = idx >> 8;
    g_wo16[idx] = __float2half_rn(Wo[co*NC + orig_ch(ci)]);
}

__global__ __launch_bounds__(256) void wtrans_kernel(
    const float* __restrict__ wq, const float* __restrict__ wk,
    const float* __restrict__ wv)
{
    const float* W = (blockIdx.y == 0) ? wq : (blockIdx.y == 1) ? wk : wv;
    __half* dst = g_wt16 + (long)blockIdx.y * 9*NC*NC;
    const int idx = blockIdx.x * 256 + threadIdx.x;
    const int ci  = idx & 255;
    const int rem = idx >> 8;
    const int co  = rem & 255;
    const int tap = rem >> 8;
    dst[idx] = __float2half_rn(W[(co*NC + orig_ch(ci))*9 + tap]);
}

__global__ __launch_bounds__(256) void stats_partial_kernel()
{
    const __half* src = g_cv16 + (long)blockIdx.y * NT*NC;
    const int c = threadIdx.x;
    float s = 0.f, s2 = 0.f;
    const int t0 = blockIdx.x * (NT/64);
    #pragma unroll 4
    for (int t = t0; t < t0 + NT/64; t++) {
        float val = __half2float(src[t*NC + c]);
        s += val; s2 += val*val;
    }
    g_part[((blockIdx.y*64 + blockIdx.x)*2 + 0)*NC + c] = s;
    g_part[((blockIdx.y*64 + blockIdx.x)*2 + 1)*NC + c] = s2;
}

__global__ __launch_bounds__(1024) void stats_final_kernel(
    const float* __restrict__ gq, const float* __restrict__ bq,
    const float* __restrict__ gk, const float* __restrict__ bk,
    const float* __restrict__ gv, const float* __restrict__ bv)
{
    const int s = blockIdx.x;
    const int c = threadIdx.x & 255;        // storage channel
    const int seg = threadIdx.x >> 8;
    float sum = 0.f, sum2 = 0.f;
    #pragma unroll
    for (int i = seg*16; i < seg*16 + 16; i++) {
        sum  += g_part[((s*64+i)*2 + 0)*NC + c];
        sum2 += g_part[((s*64+i)*2 + 1)*NC + c];
    }
    __shared__ float red[8][256];
    red[seg][c] = sum; red[4+seg][c] = sum2;
    __syncthreads();
    if (seg == 0) {
        sum  = red[0][c] + red[1][c] + red[2][c] + red[3][c];
        sum2 = red[4][c] + red[5][c] + red[6][c] + red[7][c];
        float mu  = sum  * (1.f/NT);
        float var = sum2 * (1.f/NT) - mu*mu;
        const float* gam = (s == 0) ? gq : (s == 1) ? gk : gv;
        const float* bet = (s == 0) ? bq : (s == 1) ? bk : bv;
        const int oc = orig_ch(c);
        float a  = gam[oc] * rsqrtf(var + 1e-5f);
        float bb = bet[oc] - mu*a;
        g_ab[(s*2+0)*NC + c] = a;
        g_ab[(s*2+1)*NC + c] = bb;
    }
}

__global__ __launch_bounds__(256) void fold_kernel(
    const float* __restrict__ Wq, const float* __restrict__ Wk,
    const float* __restrict__ Wv)
{
    const int s  = blockIdx.y;
    const int co = blockIdx.x;
    const int c  = threadIdx.x;            // storage channel
    const float* W = (s == 0) ? Wq : (s == 1) ? Wk : Wv;
    float a  = g_ab[(s*2+0)*NC + c];
    float bb = g_ab[(s*2+1)*NC + c];
    float wv = W[co*NC + orig_ch(c)];
    g_wf16[s*NC*NC + co*NC + c] = __float2half_rn(wv * a);

    __shared__ float red[256];
    red[c] = wv * bb;
    __syncthreads();
    for (int o = 128; o > 0; o >>= 1) {
        if (c < o) red[c] += red[c + o];
        __syncthreads();
    }
    if (c == 0) g_bf[s*NC + co] = red[0];
}

// ---------------------------------------------------------------------------

extern "C" void kernel_launch(void* const* d_in, const int* in_sizes, int n_in,
                              void* d_out, int out_size)
{
    const float* x        = (const float*)d_in[0];
    const float* y        = (const float*)d_in[1];
    const float* conv_q_w = (const float*)d_in[4];
    const float* bn_q_g   = (const float*)d_in[5];
    const float* bn_q_b   = (const float*)d_in[6];
    const float* conv_k_w = (const float*)d_in[7];
    const float* bn_k_g   = (const float*)d_in[8];
    const float* bn_k_b   = (const float*)d_in[9];
    const float* conv_v_w = (const float*)d_in[10];
    const float* bn_v_g   = (const float*)d_in[11];
    const float* bn_v_b   = (const float*)d_in[12];
    const float* Wq       = (const float*)d_in[13];
    const float* Wk       = (const float*)d_in[14];
    const float* Wv       = (const float*)d_in[15];
    const float* Wo       = (const float*)d_in[16];
    const float* bo       = (const float*)d_in[17];
    float* out = (float*)d_out;

    __half *cv16, *wf16, *ao16, *wo16;
    float *bf;
    cudaGetSymbolAddress((void**)&cv16, g_cv16);
    cudaGetSymbolAddress((void**)&wf16, g_wf16);
    cudaGetSymbolAddress((void**)&ao16, g_ao16);
    cudaGetSymbolAddress((void**)&wo16, g_wo16);
    cudaGetSymbolAddress((void**)&bf, g_bf);

    const int CONV_SMEM  = (CONV_A_H + CONV_B_H) * 2 * 2;         // 49920 B
    const int GEMM_SMEM  = (6144 + 3072) * 2 * 2;                 // 36864 B
    const int ATTN_SMEM  = (2*64*ARS + 2*32*AVS + 64*APS) * 2;    // 32768 B
    cudaFuncSetAttribute(conv_gemm_kernel,
                         cudaFuncAttributeMaxDynamicSharedMemorySize, CONV_SMEM);
    cudaFuncSetAttribute(gemm16_kernel,
                         cudaFuncAttributeMaxDynamicSharedMemorySize, GEMM_SMEM);
    cudaFuncSetAttribute(attn16_kernel,
                         cudaFuncAttributeMaxDynamicSharedMemorySize, ATTN_SMEM);

    // operand conversion + permuted weight layouts
    cvt_xy_kernel<<<dim3(NT*NC/2048, 2), 256>>>(x, y);
    wtrans_kernel<<<dim3(9*NC, 3), 256>>>(conv_q_w, conv_k_w, conv_v_w);
    round_wo_kernel<<<NC*NC/256, 256>>>(Wo);

    // 3 convs, halo implicit GEMM on fp16 tensor cores -> fp16 permuted output
    conv_gemm_kernel<<<dim3(NT/128, NC/64, 3), 256, CONV_SMEM>>>();

    // BN stats -> fold into fp16 projection weights
    stats_partial_kernel<<<dim3(64, 3), 256>>>();
    stats_final_kernel<<<3, 1024>>>(bn_q_g, bn_q_b, bn_k_g, bn_k_b, bn_v_g, bn_v_b);
    fold_kernel<<<dim3(NC, 3), 256>>>(Wq, Wk, Wv);

    // 3 projections (fp16): Q/K dim-permuted, V transposed token-permuted
    gemm16_kernel<<<dim3(NT/128, NC/64, 3), 256, GEMM_SMEM>>>(
        cv16, cv16 + (long)NT*NC, cv16 + (long)2*NT*NC,
        wf16, (long)NC*NC, bf, nullptr, 1);

    // fp16 flash attention
    attn16_kernel<<<dim3(NB*NH, NL/64), 128, ATTN_SMEM>>>();

    // output projection (fp16 GEMM, fp32 natural output)
    gemm16_kernel<<<dim3(NT/128, NC/64, 1), 256, GEMM_SMEM>>>(
        ao16, ao16, ao16, wo16, 0, bo, out, 0);
}